// round 2
// baseline (speedup 1.0000x reference)
#include <cuda_runtime.h>
#include <math.h>

#define B 16
#define CIN 3
#define DIM 128
#define KCODES 512
#define H0 256
#define H1 128
#define H2 64

// d_out layout: [recon | z_e | z_q]
#define OFF_ZE  (B*CIN*H0*H0)                  // 3145728
#define OFF_ZQ  (OFF_ZE + B*DIM*H2*H2)         // 11534336

// scratch (alloc-free rule: device globals)
__device__ float g_h[B*DIM*H1*H1];   // encoder hidden, 128 MB
__device__ float g_g[B*DIM*H1*H1];   // decoder hidden, 128 MB
__device__ float g_cnorm[KCODES];

// ---------------------------------------------------------------------------
// codebook squared norms
// ---------------------------------------------------------------------------
__global__ void knorm_kernel(const float* __restrict__ emb) {
    int k = blockIdx.x * blockDim.x + threadIdx.x;
    if (k < KCODES) {
        const float* e = emb + k * DIM;
        float s = 0.f;
#pragma unroll 8
        for (int d = 0; d < DIM; d++) s += e[d] * e[d];
        g_cnorm[k] = s;
    }
}

// ---------------------------------------------------------------------------
// conv1: x[16,3,256,256] -> h[16,128,128,128], k4 s2 p1, relu
// block = (oy, n); 256 threads = 128 oc x 2 x-halves
// ---------------------------------------------------------------------------
__global__ __launch_bounds__(256) void conv1_kernel(
    const float* __restrict__ x, const float* __restrict__ w) {
    __shared__ float ws[DIM * 48];
    __shared__ float ins[CIN][4][258];
    int n = blockIdx.y, oy = blockIdx.x;
    int tid = threadIdx.x;

    for (int i = tid; i < DIM * 48; i += 256) ws[i] = w[i];
    int iy_base = oy * 2 - 1;
    for (int i = tid; i < CIN * 4 * 258; i += 256) {
        int ic = i / 1032; int rem = i - ic * 1032;
        int r = rem / 258; int c = rem - r * 258;
        int iy = iy_base + r, ix = c - 1;
        float v = 0.f;
        if ((unsigned)iy < H0 && (unsigned)ix < H0)
            v = x[((n * CIN + ic) * H0 + iy) * H0 + ix];
        ins[ic][r][c] = v;
    }
    __syncthreads();

    int oc = tid >> 1, half = tid & 1;
    float wr[48];
#pragma unroll
    for (int k = 0; k < 48; k++) wr[k] = ws[oc * 48 + k];

    float* outp = g_h + ((n * DIM + oc) * H1 + oy) * H1;
    for (int ox = half * 64; ox < half * 64 + 64; ox++) {
        float acc = 0.f;
#pragma unroll
        for (int ic = 0; ic < 3; ic++) {
#pragma unroll
            for (int kh = 0; kh < 4; kh++) {
                const float* rp = &ins[ic][kh][0];
                float2 a0 = *(const float2*)&rp[ox * 2];
                float2 a1 = *(const float2*)&rp[ox * 2 + 2];
                const float* wk = &wr[ic * 16 + kh * 4];
                acc += wk[0] * a0.x + wk[1] * a0.y + wk[2] * a1.x + wk[3] * a1.y;
            }
        }
        outp[ox] = fmaxf(acc, 0.f);
    }
}

// ---------------------------------------------------------------------------
// conv2: h[16,128,128,128] -> z_e[16,128,64,64], k4 s2 p1 (no act)
// block = 8x8 output tile x all 128 oc; thread = 8 oc x 4 ox
// ---------------------------------------------------------------------------
__global__ __launch_bounds__(256) void conv2_kernel(
    const float* __restrict__ w, float* __restrict__ ze) {
    __shared__ float ws[DIM][64];       // [oc][ic_l*16 + kh*4 + kw]
    __shared__ float ins[4][18][21];
    int n = blockIdx.z;
    int oy0 = blockIdx.y * 8, ox0 = blockIdx.x * 8;
    int tid = threadIdx.x;
    int ocg = tid >> 4, pos = tid & 15;
    int oyl = pos >> 1, oxq = pos & 1, oxb = oxq * 4;

    float acc[8][4];
#pragma unroll
    for (int o = 0; o < 8; o++)
#pragma unroll
        for (int j = 0; j < 4; j++) acc[o][j] = 0.f;

    int iy_base = oy0 * 2 - 1, ix_base = ox0 * 2 - 1;

    for (int ic0 = 0; ic0 < DIM; ic0 += 4) {
        __syncthreads();
        for (int i = tid; i < 8192; i += 256) {
            int oc = i >> 6, k = i & 63;
            ws[oc][k] = w[oc * 2048 + ic0 * 16 + k];
        }
        for (int i = tid; i < 4 * 18 * 18; i += 256) {
            int ic = i / 324; int rem = i - ic * 324;
            int r = rem / 18; int c = rem - r * 18;
            int iy = iy_base + r, ix = ix_base + c;
            float v = 0.f;
            if ((unsigned)iy < H1 && (unsigned)ix < H1)
                v = g_h[((n * DIM + ic0 + ic) * H1 + iy) * H1 + ix];
            ins[ic][r][c] = v;
        }
        __syncthreads();
#pragma unroll
        for (int icl = 0; icl < 4; icl++) {
#pragma unroll
            for (int kh = 0; kh < 4; kh++) {
                float iv[4][4];
#pragma unroll
                for (int j = 0; j < 4; j++)
#pragma unroll
                    for (int kw = 0; kw < 4; kw++)
                        iv[j][kw] = ins[icl][oyl * 2 + kh][(oxb + j) * 2 + kw];
                int kbase = icl * 16 + kh * 4;
#pragma unroll
                for (int o = 0; o < 8; o++) {
                    float4 wq = *(const float4*)&ws[ocg * 8 + o][kbase];
#pragma unroll
                    for (int j = 0; j < 4; j++) {
                        acc[o][j] += wq.x * iv[j][0];
                        acc[o][j] += wq.y * iv[j][1];
                        acc[o][j] += wq.z * iv[j][2];
                        acc[o][j] += wq.w * iv[j][3];
                    }
                }
            }
        }
    }
    int oy = oy0 + oyl;
#pragma unroll
    for (int o = 0; o < 8; o++) {
        int oc = ocg * 8 + o;
        float* op = ze + ((n * DIM + oc) * H2 + oy) * H2;
#pragma unroll
        for (int j = 0; j < 4; j++) op[ox0 + oxb + j] = acc[o][j];
    }
}

// ---------------------------------------------------------------------------
// VQ: per 64-vector block: argmin over 512 codes of (||c||^2 - 2 z.c), then
// gather z_q = emb[idx] back into NCHW. Dynamic smem: z[128][64] + c[128][132]
// ---------------------------------------------------------------------------
__global__ __launch_bounds__(256) void vq_kernel(
    const float* __restrict__ ze, const float* __restrict__ emb,
    float* __restrict__ zq) {
    extern __shared__ float sm[];
    float* z_s = sm;                 // [d][64]
    float* c_s = sm + 128 * 64;      // [d][132] (padded)
    __shared__ int idx_s[64];

    int tid = threadIdx.x;
    int v0 = blockIdx.x * 64;
    int b = v0 >> 12;            // 4096 spatial per batch
    int s0 = v0 & 4095;

    for (int i = tid; i < 8192; i += 256) {
        int d = i >> 6, vl = i & 63;
        z_s[d * 64 + vl] = ze[(b * DIM + d) * 4096 + s0 + vl];
    }

    int vg = tid >> 4, cg = tid & 15;   // 16 vec-groups x 16 code-groups
    float minv[4] = {3.0e38f, 3.0e38f, 3.0e38f, 3.0e38f};
    int mini[4] = {0, 0, 0, 0};

    for (int ch = 0; ch < 4; ch++) {
        __syncthreads();
        int cbase = ch * 128;
        for (int i = tid; i < 16384; i += 256) {
            int cl = i >> 7, d = i & 127;
            c_s[d * 132 + cl] = emb[(cbase + cl) * DIM + d];
        }
        __syncthreads();

        float dot[4][8];
#pragma unroll
        for (int v = 0; v < 4; v++)
#pragma unroll
            for (int c = 0; c < 8; c++) dot[v][c] = 0.f;

#pragma unroll 4
        for (int d = 0; d < 128; d++) {
            float4 zv = *(const float4*)&z_s[d * 64 + vg * 4];
            float4 c0 = *(const float4*)&c_s[d * 132 + cg * 8];
            float4 c1 = *(const float4*)&c_s[d * 132 + cg * 8 + 4];
            float zz[4] = {zv.x, zv.y, zv.z, zv.w};
            float cc[8] = {c0.x, c0.y, c0.z, c0.w, c1.x, c1.y, c1.z, c1.w};
#pragma unroll
            for (int v = 0; v < 4; v++)
#pragma unroll
                for (int c = 0; c < 8; c++) dot[v][c] += zz[v] * cc[c];
        }
#pragma unroll
        for (int c = 0; c < 8; c++) {
            int code = cbase + cg * 8 + c;
            float cn = g_cnorm[code];
#pragma unroll
            for (int v = 0; v < 4; v++) {
                float dd = cn - 2.f * dot[v][c];
                if (dd < minv[v]) { minv[v] = dd; mini[v] = code; }
            }
        }
    }

    __syncthreads();
    float* red_d = c_s;                  // reuse
    int* red_i = (int*)(c_s + 1024);
#pragma unroll
    for (int v = 0; v < 4; v++) {
        int vl = vg * 4 + v;
        red_d[vl * 16 + cg] = minv[v];
        red_i[vl * 16 + cg] = mini[v];
    }
    __syncthreads();
    if (tid < 64) {
        float bd = red_d[tid * 16]; int bi = red_i[tid * 16];
        for (int g = 1; g < 16; g++) {
            float d2 = red_d[tid * 16 + g]; int i2 = red_i[tid * 16 + g];
            if (d2 < bd || (d2 == bd && i2 < bi)) { bd = d2; bi = i2; }
        }
        idx_s[tid] = bi;
    }
    __syncthreads();
    for (int i = tid; i < 8192; i += 256) {
        int d = i >> 6, vl = i & 63;
        zq[(b * DIM + d) * 4096 + s0 + vl] = __ldg(&emb[idx_s[vl] * DIM + d]);
    }
}

// ---------------------------------------------------------------------------
// deconv1: z_q[16,128,64,64] -> g[16,128,128,128], transposed k4 s2 p1, relu
// parity trick: out (p,q) uses kh in {a,a+2}, kw in {b,b+2}, a=p&1, b=q&1
// block = 8x8 out tile x 128 oc; thread = 8 oc x 4 q-positions (same parity)
// ---------------------------------------------------------------------------
__global__ __launch_bounds__(256) void deconv1_kernel(
    const float* __restrict__ w, const float* __restrict__ zq) {
    __shared__ float ws[DIM][64];   // [oc][ic_l*16 + kh*4 + kw]
    __shared__ float ins[4][6][8];
    int n = blockIdx.z;
    int p0 = blockIdx.y * 8, q0 = blockIdx.x * 8;
    int tid = threadIdx.x;
    int ocg = tid >> 4, pos = tid & 15;
    int pl = pos >> 1, qp = pos & 1;
    int a = pl & 1;
    int r0l = (pl + a) >> 1;
    int rb = p0 / 2 - 1, cb = q0 / 2 - 1;

    float acc[8][4];
#pragma unroll
    for (int o = 0; o < 8; o++)
#pragma unroll
        for (int j = 0; j < 4; j++) acc[o][j] = 0.f;

    for (int ic0 = 0; ic0 < DIM; ic0 += 4) {
        __syncthreads();
        for (int i = tid; i < 8192; i += 256) {
            int oc = i >> 6, k = i & 63;
            ws[oc][k] = w[oc * 2048 + ic0 * 16 + k];
        }
        for (int i = tid; i < 144; i += 256) {
            int ic = i / 36; int rem = i - ic * 36;
            int r = rem / 6, c = rem - r * 6;
            int rr = rb + r, cc = cb + c;
            float v = 0.f;
            if ((unsigned)rr < H2 && (unsigned)cc < H2)
                v = zq[((n * DIM + ic0 + ic) * H2 + rr) * H2 + cc];
            ins[ic][r][c] = v;
        }
        __syncthreads();
#pragma unroll
        for (int icl = 0; icl < 4; icl++) {
            float rin[2][5];
#pragma unroll
            for (int s = 0; s < 2; s++)
#pragma unroll
                for (int m = 0; m < 5; m++)
                    rin[s][m] = ins[icl][r0l + s][qp + m];
            int kb = icl * 16 + a * 4 + qp;
#pragma unroll
            for (int o = 0; o < 8; o++) {
                const float* wrow = &ws[ocg * 8 + o][kb];
                float w00 = wrow[0];   // kh=a,   kw=b
                float w01 = wrow[2];   // kh=a,   kw=b+2
                float w10 = wrow[8];   // kh=a+2, kw=b
                float w11 = wrow[10];  // kh=a+2, kw=b+2
#pragma unroll
                for (int j = 0; j < 4; j++) {
                    acc[o][j] += w00 * rin[0][j] + w01 * rin[0][j + 1]
                               + w10 * rin[1][j] + w11 * rin[1][j + 1];
                }
            }
        }
    }
    int p = p0 + pl;
#pragma unroll
    for (int o = 0; o < 8; o++) {
        int oc = ocg * 8 + o;
        float* op = g_g + ((n * DIM + oc) * H1 + p) * H1;
#pragma unroll
        for (int j = 0; j < 4; j++) {
            int q = q0 + qp + 2 * j;
            op[q] = fmaxf(acc[o][j], 0.f);
        }
    }
}

// ---------------------------------------------------------------------------
// deconv2: g[16,128,128,128] -> recon[16,3,256,256], transposed k4 s2 p1, tanh
// block = 16x16 out tile x 3 oc; thread = 1 position x 3 oc
// ---------------------------------------------------------------------------
__global__ __launch_bounds__(256) void deconv2_kernel(
    const float* __restrict__ w, float* __restrict__ recon) {
    __shared__ float ws[CIN * DIM * 16];   // full weights, 24 KB
    __shared__ float ins[8][10][12];
    int n = blockIdx.z;
    int p0 = blockIdx.y * 16, q0 = blockIdx.x * 16;
    int tid = threadIdx.x;
    int pl = tid >> 4, ql = tid & 15;
    int a = pl & 1, bb = ql & 1;
    int r0l = (pl + a) >> 1, c0l = (ql + bb) >> 1;
    int rb = p0 / 2 - 1, cb = q0 / 2 - 1;

    for (int i = tid; i < CIN * DIM * 16; i += 256) ws[i] = w[i];

    float acc[3] = {0.f, 0.f, 0.f};
    for (int ic0 = 0; ic0 < DIM; ic0 += 8) {
        __syncthreads();
        for (int i = tid; i < 800; i += 256) {
            int ic = i / 100; int rem = i - ic * 100;
            int r = rem / 10, c = rem - r * 10;
            int rr = rb + r, cc = cb + c;
            float v = 0.f;
            if ((unsigned)rr < H1 && (unsigned)cc < H1)
                v = g_g[((n * DIM + ic0 + ic) * H1 + rr) * H1 + cc];
            ins[ic][r][c] = v;
        }
        __syncthreads();
#pragma unroll
        for (int icl = 0; icl < 8; icl++) {
            float i00 = ins[icl][r0l][c0l],     i01 = ins[icl][r0l][c0l + 1];
            float i10 = ins[icl][r0l + 1][c0l], i11 = ins[icl][r0l + 1][c0l + 1];
            int kb = (ic0 + icl) * 16 + a * 4 + bb;
#pragma unroll
            for (int o = 0; o < 3; o++) {
                const float* wr = &ws[o * 2048 + kb];
                acc[o] += wr[0] * i00 + wr[2] * i01 + wr[8] * i10 + wr[10] * i11;
            }
        }
    }
    int p = p0 + pl, q = q0 + ql;
#pragma unroll
    for (int o = 0; o < 3; o++)
        recon[((n * CIN + o) * H0 + p) * H0 + q] = tanhf(acc[o]);
}

// ---------------------------------------------------------------------------
#define VQ_SMEM ((128 * 64 + 128 * 132) * (int)sizeof(float))   // 100352 B

extern "C" void kernel_launch(void* const* d_in, const int* in_sizes, int n_in,
                              void* d_out, int out_size) {
    const float* x    = (const float*)d_in[0];
    const float* w_e1 = (const float*)d_in[1];
    const float* w_e2 = (const float*)d_in[2];
    const float* emb  = (const float*)d_in[3];
    const float* w_d1 = (const float*)d_in[4];
    const float* w_d2 = (const float*)d_in[5];

    float* out   = (float*)d_out;
    float* recon = out;
    float* ze    = out + OFF_ZE;
    float* zq    = out + OFF_ZQ;

    cudaFuncSetAttribute(vq_kernel, cudaFuncAttributeMaxDynamicSharedMemorySize,
                         VQ_SMEM);

    knorm_kernel<<<2, 256>>>(emb);
    conv1_kernel<<<dim3(H1, B), 256>>>(x, w_e1);
    conv2_kernel<<<dim3(8, 8, B), 256>>>(w_e2, ze);
    vq_kernel<<<1024, 256, VQ_SMEM>>>(ze, emb, zq);
    deconv1_kernel<<<dim3(16, 16, B), 256>>>(w_d1, zq);
    deconv2_kernel<<<dim3(16, 16, B), 256>>>(w_d2, recon);
}

// round 3
// speedup vs baseline: 1.1595x; 1.1595x over previous
#include <cuda_runtime.h>
#include <math.h>

#define B 16
#define CIN 3
#define DIM 128
#define KCODES 512
#define H0 256
#define H1 128
#define H2 64

#define OFF_ZE  (B*CIN*H0*H0)
#define OFF_ZQ  (OFF_ZE + B*DIM*H2*H2)

__device__ float g_h[B*DIM*H1*H1];
__device__ float g_g[B*DIM*H1*H1];
__device__ float g_cnorm[KCODES];

typedef unsigned long long u64;
__device__ __forceinline__ void fma2(u64& d, u64 a, u64 b) {
    asm("fma.rn.f32x2 %0, %1, %2, %0;" : "+l"(d) : "l"(a), "l"(b));
}
__device__ __forceinline__ u64 pack2(float lo, float hi) {
    u64 r; asm("mov.b64 %0, {%1, %2};" : "=l"(r) : "f"(lo), "f"(hi)); return r;
}
__device__ __forceinline__ float2 unpack2(u64 v) {
    float2 r; asm("mov.b64 {%0, %1}, %2;" : "=f"(r.x), "=f"(r.y) : "l"(v)); return r;
}
__device__ __forceinline__ u64 lds2(const float* p) {
    return *reinterpret_cast<const u64*>(p);
}

// ---------------------------------------------------------------------------
__global__ void knorm_kernel(const float* __restrict__ emb) {
    int k = blockIdx.x * blockDim.x + threadIdx.x;
    if (k < KCODES) {
        const float* e = emb + k * DIM;
        float s = 0.f;
#pragma unroll 8
        for (int d = 0; d < DIM; d++) s += e[d] * e[d];
        g_cnorm[k] = s;
    }
}

// ---------------------------------------------------------------------------
// conv1: x[16,3,256,256] -> h, k4 s2 p1, relu. f32x2 over kw pairs.
// ---------------------------------------------------------------------------
__global__ __launch_bounds__(256) void conv1_kernel(
    const float* __restrict__ x, const float* __restrict__ w) {
    __shared__ float ws[DIM * 48];
    __shared__ float ins[CIN][4][260];
    int n = blockIdx.y, oy = blockIdx.x;
    int tid = threadIdx.x;

    for (int i = tid; i < DIM * 48; i += 256) ws[i] = w[i];
    int iy_base = oy * 2 - 1;
    for (int i = tid; i < CIN * 4 * 258; i += 256) {
        int ic = i / 1032; int rem = i - ic * 1032;
        int r = rem / 258; int c = rem - r * 258;
        int iy = iy_base + r, ix = c - 1;
        float v = 0.f;
        if ((unsigned)iy < H0 && (unsigned)ix < H0)
            v = x[((n * CIN + ic) * H0 + iy) * H0 + ix];
        ins[ic][r][c] = v;
    }
    __syncthreads();

    int oc = tid >> 1, half = tid & 1;
    u64 wp[24];
#pragma unroll
    for (int ic = 0; ic < 3; ic++)
#pragma unroll
        for (int kh = 0; kh < 4; kh++) {
            const float* wk = &ws[oc * 48 + ic * 16 + kh * 4];
            wp[(ic * 4 + kh) * 2 + 0] = pack2(wk[0], wk[1]);
            wp[(ic * 4 + kh) * 2 + 1] = pack2(wk[2], wk[3]);
        }

    float* outp = g_h + ((n * DIM + oc) * H1 + oy) * H1;
    for (int k = 0; k < 64; k += 2) {
        int oxa = half + 2 * k, oxb = oxa + 2;
        u64 acca = 0ULL, accb = 0ULL;
#pragma unroll
        for (int ic = 0; ic < 3; ic++)
#pragma unroll
            for (int kh = 0; kh < 4; kh++) {
                const float* rp = &ins[ic][kh][0];
                u64 w01 = wp[(ic * 4 + kh) * 2 + 0];
                u64 w23 = wp[(ic * 4 + kh) * 2 + 1];
                fma2(acca, lds2(rp + 2 * oxa),     w01);
                fma2(acca, lds2(rp + 2 * oxa + 2), w23);
                fma2(accb, lds2(rp + 2 * oxb),     w01);
                fma2(accb, lds2(rp + 2 * oxb + 2), w23);
            }
        float2 va = unpack2(acca), vb = unpack2(accb);
        outp[oxa] = fmaxf(va.x + va.y, 0.f);
        outp[oxb] = fmaxf(vb.x + vb.y, 0.f);
    }
}

// ---------------------------------------------------------------------------
// conv2: h -> z_e, k4 s2 p1. Tile 8x8, thread = 4 oc x 8 ox. f32x2 kw pairs,
// deduped input loads (9 LDS.64 per (ic,kh)).
// ---------------------------------------------------------------------------
__global__ __launch_bounds__(256) void conv2_kernel(
    const float* __restrict__ w, float* __restrict__ ze) {
    __shared__ float ws[DIM][68];
    __shared__ float ins[4][18][22];
    int n = blockIdx.z;
    int oy0 = blockIdx.y * 8, ox0 = blockIdx.x * 8;
    int tid = threadIdx.x;
    int ocg = tid >> 3, oyl = tid & 7;

    u64 acc[4][8];
#pragma unroll
    for (int o = 0; o < 4; o++)
#pragma unroll
        for (int j = 0; j < 8; j++) acc[o][j] = 0ULL;

    int iy_base = oy0 * 2 - 1, ix_base = ox0 * 2 - 1;

    for (int ic0 = 0; ic0 < DIM; ic0 += 4) {
        __syncthreads();
        for (int i = tid; i < 8192; i += 256) {
            int oc = i >> 6, k = i & 63;
            ws[oc][k] = w[oc * 2048 + ic0 * 16 + k];
        }
        for (int i = tid; i < 4 * 18 * 18; i += 256) {
            int ic = i / 324; int rem = i - ic * 324;
            int r = rem / 18; int c = rem - r * 18;
            int iy = iy_base + r, ix = ix_base + c;
            float v = 0.f;
            if ((unsigned)iy < H1 && (unsigned)ix < H1)
                v = g_h[((n * DIM + ic0 + ic) * H1 + iy) * H1 + ix];
            ins[ic][r][c] = v;
        }
        __syncthreads();
#pragma unroll
        for (int icl = 0; icl < 4; icl++) {
#pragma unroll
            for (int kh = 0; kh < 4; kh++) {
                const float* rp = &ins[icl][oyl * 2 + kh][0];
                u64 ivp[9];
#pragma unroll
                for (int m = 0; m < 9; m++) ivp[m] = lds2(rp + 2 * m);
#pragma unroll
                for (int o = 0; o < 4; o++) {
                    const float* wpt = &ws[ocg * 4 + o][icl * 16 + kh * 4];
                    u64 w01 = lds2(wpt);
                    u64 w23 = lds2(wpt + 2);
#pragma unroll
                    for (int j = 0; j < 8; j++) {
                        fma2(acc[o][j], ivp[j],     w01);
                        fma2(acc[o][j], ivp[j + 1], w23);
                    }
                }
            }
        }
    }
    int oy = oy0 + oyl;
#pragma unroll
    for (int o = 0; o < 4; o++) {
        int oc = ocg * 4 + o;
        float* op = ze + ((n * DIM + oc) * H2 + oy) * H2 + ox0;
#pragma unroll
        for (int j = 0; j < 8; j++) {
            float2 v = unpack2(acc[o][j]);
            op[j] = v.x + v.y;
        }
    }
}

// ---------------------------------------------------------------------------
// VQ: 128 vectors/block, 256 threads, 8 vec x 8 code per thread, f32x2.
// ---------------------------------------------------------------------------
__global__ __launch_bounds__(256) void vq_kernel(
    const float* __restrict__ ze, const float* __restrict__ emb,
    float* __restrict__ zq) {
    extern __shared__ float sm[];
    float* z_s = sm;                  // [128][132]
    float* c_s = sm + 128 * 132;      // [128][132]
    __shared__ int idx_s[128];

    int tid = threadIdx.x;
    int v0 = blockIdx.x * 128;
    int b = v0 >> 12;
    int s0 = v0 & 4095;

    for (int i = tid; i < 4096; i += 256) {
        int d = i >> 5, vl4 = (i & 31) * 4;
        float4 t = *(const float4*)&ze[(b * DIM + d) * 4096 + s0 + vl4];
        *(float4*)&z_s[d * 132 + vl4] = t;
    }

    int vg = tid >> 4, cg = tid & 15;
    float minv[8];
    int mini[8];
#pragma unroll
    for (int v = 0; v < 8; v++) { minv[v] = 3.0e38f; mini[v] = 0; }

    u64 dot[4][8];
#pragma unroll
    for (int vp = 0; vp < 4; vp++)
#pragma unroll
        for (int c = 0; c < 8; c++) dot[vp][c] = 0ULL;

    for (int ch = 0; ch < 4; ch++) {
        __syncthreads();
        int cbase = ch * 128;
        for (int i = tid; i < 4096; i += 256) {
            int cl = i & 127, dq = (i >> 7) * 4;
            float4 t = *(const float4*)&emb[(cbase + cl) * DIM + dq];
            c_s[(dq + 0) * 132 + cl] = t.x;
            c_s[(dq + 1) * 132 + cl] = t.y;
            c_s[(dq + 2) * 132 + cl] = t.z;
            c_s[(dq + 3) * 132 + cl] = t.w;
        }
        __syncthreads();

#pragma unroll 2
        for (int d = 0; d < 128; d++) {
            const float* zp = &z_s[d * 132 + vg * 8];
            float4 z0 = *(const float4*)zp;
            float4 z1 = *(const float4*)(zp + 4);
            u64 zpk[4];
            zpk[0] = pack2(z0.x, z0.y); zpk[1] = pack2(z0.z, z0.w);
            zpk[2] = pack2(z1.x, z1.y); zpk[3] = pack2(z1.z, z1.w);
            const float* cp = &c_s[d * 132];
            float4 c0 = *(const float4*)(cp + cg * 4);
            float4 c1 = *(const float4*)(cp + 64 + cg * 4);
            u64 cb[8];
            cb[0] = pack2(c0.x, c0.x); cb[1] = pack2(c0.y, c0.y);
            cb[2] = pack2(c0.z, c0.z); cb[3] = pack2(c0.w, c0.w);
            cb[4] = pack2(c1.x, c1.x); cb[5] = pack2(c1.y, c1.y);
            cb[6] = pack2(c1.z, c1.z); cb[7] = pack2(c1.w, c1.w);
#pragma unroll
            for (int vp = 0; vp < 4; vp++)
#pragma unroll
                for (int c = 0; c < 8; c++) fma2(dot[vp][c], zpk[vp], cb[c]);
        }

#pragma unroll
        for (int c = 0; c < 8; c++) {
            int code = cbase + (c < 4 ? cg * 4 + c : 64 + cg * 4 + (c - 4));
            float cn = g_cnorm[code];
#pragma unroll
            for (int vp = 0; vp < 4; vp++) {
                float2 dv = unpack2(dot[vp][c]);
                float d0 = fmaf(-2.f, dv.x, cn);
                float d1 = fmaf(-2.f, dv.y, cn);
                if (d0 < minv[2 * vp])     { minv[2 * vp] = d0;     mini[2 * vp] = code; }
                if (d1 < minv[2 * vp + 1]) { minv[2 * vp + 1] = d1; mini[2 * vp + 1] = code; }
                dot[vp][c] = 0ULL;
            }
        }
    }

    __syncthreads();
    float* red_d = c_s;
    int* red_i = (int*)(c_s + 2048);
#pragma unroll
    for (int v = 0; v < 8; v++) {
        int vl = vg * 8 + v;
        red_d[vl * 16 + cg] = minv[v];
        red_i[vl * 16 + cg] = mini[v];
    }
    __syncthreads();
    if (tid < 128) {
        float bd = red_d[tid * 16]; int bi = red_i[tid * 16];
        for (int g = 1; g < 16; g++) {
            float d2 = red_d[tid * 16 + g]; int i2 = red_i[tid * 16 + g];
            if (d2 < bd || (d2 == bd && i2 < bi)) { bd = d2; bi = i2; }
        }
        idx_s[tid] = bi;
    }
    __syncthreads();
    for (int i = tid; i < 16384; i += 256) {
        int d = i >> 7, vl = i & 127;
        zq[(b * DIM + d) * 4096 + s0 + vl] = __ldg(&emb[idx_s[vl] * DIM + d]);
    }
}

// ---------------------------------------------------------------------------
// deconv1: z_q -> g, transposed k4 s2 p1, relu. Tile 8p x 16q, 4 oc/thread.
// Parity-permuted weights: 4 taps of a parity group = one LDS.128.
// Accumulators packed over q-pairs (q, q+2).
// ---------------------------------------------------------------------------
__global__ __launch_bounds__(256) void deconv1_kernel(
    const float* __restrict__ w, const float* __restrict__ zq) {
    __shared__ float ws[DIM][68];
    __shared__ float ins[4][6][12];
    int n = blockIdx.z;
    int q0 = blockIdx.x * 16, p0 = blockIdx.y * 8;
    int tid = threadIdx.x;
    int ocg = tid >> 3, pl = tid & 7;
    int a = pl & 1;
    int r0l = (pl + a) >> 1;
    int rb = p0 / 2 - 1, cb = q0 / 2 - 1;

    u64 acc[4][2][4];
#pragma unroll
    for (int o = 0; o < 4; o++)
#pragma unroll
        for (int qp = 0; qp < 2; qp++)
#pragma unroll
            for (int jp = 0; jp < 4; jp++) acc[o][qp][jp] = 0ULL;

    for (int ic0 = 0; ic0 < DIM; ic0 += 4) {
        __syncthreads();
        for (int i = tid; i < 8192; i += 256) {
            int oc = i >> 6, k = i & 63;
            int icl = k >> 4, kk = k & 15, kh = kk >> 2, kw = kk & 3;
            int slot = icl * 16 + ((kh & 1) * 2 + (kw & 1)) * 4
                     + ((kh >> 1) << 1) + (kw >> 1);
            ws[oc][slot] = w[oc * 2048 + ic0 * 16 + k];
        }
        for (int i = tid; i < 240; i += 256) {
            int ic = i / 60; int rem = i - ic * 60;
            int r = rem / 10, c = rem - r * 10;
            int rr = rb + r, cc = cb + c;
            float v = 0.f;
            if ((unsigned)rr < H2 && (unsigned)cc < H2)
                v = zq[((n * DIM + ic0 + ic) * H2 + rr) * H2 + cc];
            ins[ic][r][c] = v;
        }
        __syncthreads();
#pragma unroll
        for (int icl = 0; icl < 4; icl++) {
            float rin0[10], rin1[10];
#pragma unroll
            for (int m = 0; m < 10; m++) {
                rin0[m] = ins[icl][r0l][m];
                rin1[m] = ins[icl][r0l + 1][m];
            }
            u64 ip0[9], ip1[9];
#pragma unroll
            for (int m = 0; m < 9; m++) {
                ip0[m] = pack2(rin0[m], rin0[m + 1]);
                ip1[m] = pack2(rin1[m], rin1[m + 1]);
            }
#pragma unroll
            for (int o = 0; o < 4; o++) {
                const float* wpt = &ws[ocg * 4 + o][icl * 16 + a * 8];
                float4 wg0 = *(const float4*)(wpt);       // parity (a, b=0)
                float4 wg1 = *(const float4*)(wpt + 4);   // parity (a, b=1)
                u64 b00 = pack2(wg0.x, wg0.x), b01 = pack2(wg0.y, wg0.y);
                u64 b10 = pack2(wg0.z, wg0.z), b11 = pack2(wg0.w, wg0.w);
                u64 c00 = pack2(wg1.x, wg1.x), c01 = pack2(wg1.y, wg1.y);
                u64 c10 = pack2(wg1.z, wg1.z), c11 = pack2(wg1.w, wg1.w);
#pragma unroll
                for (int jp = 0; jp < 4; jp++) {
                    fma2(acc[o][0][jp], ip0[2 * jp + 0], b00);
                    fma2(acc[o][0][jp], ip0[2 * jp + 1], b01);
                    fma2(acc[o][0][jp], ip1[2 * jp + 0], b10);
                    fma2(acc[o][0][jp], ip1[2 * jp + 1], b11);
                    fma2(acc[o][1][jp], ip0[2 * jp + 1], c00);
                    fma2(acc[o][1][jp], ip0[2 * jp + 2], c01);
                    fma2(acc[o][1][jp], ip1[2 * jp + 1], c10);
                    fma2(acc[o][1][jp], ip1[2 * jp + 2], c11);
                }
            }
        }
    }
    int p = p0 + pl;
#pragma unroll
    for (int o = 0; o < 4; o++) {
        int oc = ocg * 4 + o;
        float* op = g_g + ((n * DIM + oc) * H1 + p) * H1 + q0;
#pragma unroll
        for (int qp = 0; qp < 2; qp++)
#pragma unroll
            for (int jp = 0; jp < 4; jp++) {
                float2 v = unpack2(acc[o][qp][jp]);
                op[qp + 4 * jp]     = fmaxf(v.x, 0.f);
                op[qp + 4 * jp + 2] = fmaxf(v.y, 0.f);
            }
    }
}

// ---------------------------------------------------------------------------
// deconv2: g -> recon, transposed k4 s2 p1, tanh. Tile 16p x 32q, thread =
// one q-pair (q, q+2) x 3 oc, f32x2 packed, parity-permuted weights.
// ---------------------------------------------------------------------------
__global__ __launch_bounds__(256) void deconv2_kernel(
    const float* __restrict__ w, float* __restrict__ recon) {
    __shared__ float wsp[CIN][DIM * 16];   // permuted, 24 KB
    __shared__ float ins[8][10][20];
    int n = blockIdx.z;
    int p0 = blockIdx.y * 16, q0 = blockIdx.x * 32;
    int tid = threadIdx.x;
    int pl = tid >> 4, qi = tid & 15;
    int qp = qi & 1, jj = qi >> 1;
    int a = pl & 1;
    int r0l = (pl + a) >> 1;
    int c0l = qp + 2 * jj;
    int rb = p0 / 2 - 1, cb = q0 / 2 - 1;

    for (int i = tid; i < CIN * DIM * 16; i += 256) {
        int oc = i >> 11, rem = i & 2047;
        int ic = rem >> 4, k = rem & 15, kh = k >> 2, kw = k & 3;
        int slot = ic * 16 + ((kh & 1) * 2 + (kw & 1)) * 4
                 + ((kh >> 1) << 1) + (kw >> 1);
        wsp[oc][slot] = w[i];
    }

    u64 acc[3] = {0ULL, 0ULL, 0ULL};
    for (int ic0 = 0; ic0 < DIM; ic0 += 8) {
        __syncthreads();
        for (int i = tid; i < 8 * 10 * 18; i += 256) {
            int ic = i / 180; int rem = i - ic * 180;
            int r = rem / 18, c = rem - r * 18;
            int rr = rb + r, cc = cb + c;
            float v = 0.f;
            if ((unsigned)rr < H1 && (unsigned)cc < H1)
                v = g_g[((n * DIM + ic0 + ic) * H1 + rr) * H1 + cc];
            ins[ic][r][c] = v;
        }
        __syncthreads();
#pragma unroll
        for (int icl = 0; icl < 8; icl++) {
            float t00 = ins[icl][r0l][c0l],     t01 = ins[icl][r0l][c0l + 1];
            float t02 = ins[icl][r0l][c0l + 2];
            float t10 = ins[icl][r0l + 1][c0l], t11 = ins[icl][r0l + 1][c0l + 1];
            float t12 = ins[icl][r0l + 1][c0l + 2];
            u64 i0a = pack2(t00, t01), i0b = pack2(t01, t02);
            u64 i1a = pack2(t10, t11), i1b = pack2(t11, t12);
            int kb = (ic0 + icl) * 16 + (a * 2 + qp) * 4;
#pragma unroll
            for (int o = 0; o < 3; o++) {
                float4 wg = *(const float4*)&wsp[o][kb];
                fma2(acc[o], i0a, pack2(wg.x, wg.x));
                fma2(acc[o], i0b, pack2(wg.y, wg.y));
                fma2(acc[o], i1a, pack2(wg.z, wg.z));
                fma2(acc[o], i1b, pack2(wg.w, wg.w));
            }
        }
    }
    int p = p0 + pl, q = q0 + qp + 4 * jj;
#pragma unroll
    for (int o = 0; o < 3; o++) {
        float2 v = unpack2(acc[o]);
        float* op = recon + ((n * CIN + o) * H0 + p) * H0;
        op[q]     = tanhf(v.x);
        op[q + 2] = tanhf(v.y);
    }
}

// ---------------------------------------------------------------------------
#define VQ_SMEM (2 * 128 * 132 * (int)sizeof(float))   // 135168 B

extern "C" void kernel_launch(void* const* d_in, const int* in_sizes, int n_in,
                              void* d_out, int out_size) {
    const float* x    = (const float*)d_in[0];
    const float* w_e1 = (const float*)d_in[1];
    const float* w_e2 = (const float*)d_in[2];
    const float* emb  = (const float*)d_in[3];
    const float* w_d1 = (const float*)d_in[4];
    const float* w_d2 = (const float*)d_in[5];

    float* out   = (float*)d_out;
    float* recon = out;
    float* ze    = out + OFF_ZE;
    float* zq    = out + OFF_ZQ;

    cudaFuncSetAttribute(vq_kernel, cudaFuncAttributeMaxDynamicSharedMemorySize,
                         VQ_SMEM);

    knorm_kernel<<<2, 256>>>(emb);
    conv1_kernel<<<dim3(H1, B), 256>>>(x, w_e1);
    conv2_kernel<<<dim3(8, 8, B), 256>>>(w_e2, ze);
    vq_kernel<<<512, 256, VQ_SMEM>>>(ze, emb, zq);
    deconv1_kernel<<<dim3(8, 16, B), 256>>>(w_d1, zq);
    deconv2_kernel<<<dim3(8, 16, B), 256>>>(w_d2, recon);
}

// round 4
// speedup vs baseline: 1.1609x; 1.0012x over previous
#include <cuda_runtime.h>
#include <math.h>

#define B 16
#define CIN 3
#define DIM 128
#define KCODES 512
#define H0 256
#define H1 128
#define H2 64

#define OFF_ZE  (B*CIN*H0*H0)
#define OFF_ZQ  (OFF_ZE + B*DIM*H2*H2)

__device__ float g_h[B*DIM*H1*H1];
__device__ float g_g[B*DIM*H1*H1];
__device__ float g_cnorm[KCODES];

typedef unsigned long long u64;
__device__ __forceinline__ void fma2(u64& d, u64 a, u64 b) {
    asm("fma.rn.f32x2 %0, %1, %2, %0;" : "+l"(d) : "l"(a), "l"(b));
}
__device__ __forceinline__ u64 pack2(float lo, float hi) {
    u64 r; asm("mov.b64 %0, {%1, %2};" : "=l"(r) : "f"(lo), "f"(hi)); return r;
}
__device__ __forceinline__ float2 unpack2(u64 v) {
    float2 r; asm("mov.b64 {%0, %1}, %2;" : "=f"(r.x), "=f"(r.y) : "l"(v)); return r;
}
__device__ __forceinline__ u64 lds2(const float* p) {
    return *reinterpret_cast<const u64*>(p);
}

// ---------------------------------------------------------------------------
__global__ void knorm_kernel(const float* __restrict__ emb) {
    int k = blockIdx.x * blockDim.x + threadIdx.x;
    if (k < KCODES) {
        const float* e = emb + k * DIM;
        float s = 0.f;
#pragma unroll 8
        for (int d = 0; d < DIM; d++) s += e[d] * e[d];
        g_cnorm[k] = s;
    }
}

// ---------------------------------------------------------------------------
// conv1: x[16,3,256,256] -> h, k4 s2 p1, relu. f32x2 over kw pairs.
// ---------------------------------------------------------------------------
__global__ __launch_bounds__(256) void conv1_kernel(
    const float* __restrict__ x, const float* __restrict__ w) {
    __shared__ float ws[DIM * 48];
    __shared__ float ins[CIN][4][260];
    int n = blockIdx.y, oy = blockIdx.x;
    int tid = threadIdx.x;

    for (int i = tid; i < DIM * 48; i += 256) ws[i] = w[i];
    int iy_base = oy * 2 - 1;
    for (int i = tid; i < CIN * 4 * 258; i += 256) {
        int ic = i / 1032; int rem = i - ic * 1032;
        int r = rem / 258; int c = rem - r * 258;
        int iy = iy_base + r, ix = c - 1;
        float v = 0.f;
        if ((unsigned)iy < H0 && (unsigned)ix < H0)
            v = x[((n * CIN + ic) * H0 + iy) * H0 + ix];
        ins[ic][r][c] = v;
    }
    __syncthreads();

    int oc = tid >> 1, half = tid & 1;
    u64 wp[24];
#pragma unroll
    for (int ic = 0; ic < 3; ic++)
#pragma unroll
        for (int kh = 0; kh < 4; kh++) {
            const float* wk = &ws[oc * 48 + ic * 16 + kh * 4];
            wp[(ic * 4 + kh) * 2 + 0] = pack2(wk[0], wk[1]);
            wp[(ic * 4 + kh) * 2 + 1] = pack2(wk[2], wk[3]);
        }

    float* outp = g_h + ((n * DIM + oc) * H1 + oy) * H1;
    for (int k = 0; k < 64; k += 2) {
        int oxa = half + 2 * k, oxb = oxa + 2;
        u64 acca = 0ULL, accb = 0ULL;
#pragma unroll
        for (int ic = 0; ic < 3; ic++)
#pragma unroll
            for (int kh = 0; kh < 4; kh++) {
                const float* rp = &ins[ic][kh][0];
                u64 w01 = wp[(ic * 4 + kh) * 2 + 0];
                u64 w23 = wp[(ic * 4 + kh) * 2 + 1];
                fma2(acca, lds2(rp + 2 * oxa),     w01);
                fma2(acca, lds2(rp + 2 * oxa + 2), w23);
                fma2(accb, lds2(rp + 2 * oxb),     w01);
                fma2(accb, lds2(rp + 2 * oxb + 2), w23);
            }
        float2 va = unpack2(acca), vb = unpack2(accb);
        outp[oxa] = fmaxf(va.x + va.y, 0.f);
        outp[oxb] = fmaxf(vb.x + vb.y, 0.f);
    }
}

// ---------------------------------------------------------------------------
// conv2: h -> z_e, k4 s2 p1. Tile 8x8, thread = 4 oc x 8 ox. f32x2 kw pairs,
// deduped input loads (9 LDS.64 per (ic,kh)).
// ---------------------------------------------------------------------------
__global__ __launch_bounds__(256) void conv2_kernel(
    const float* __restrict__ w, float* __restrict__ ze) {
    __shared__ float ws[DIM][68];
    __shared__ float ins[4][18][22];
    int n = blockIdx.z;
    int oy0 = blockIdx.y * 8, ox0 = blockIdx.x * 8;
    int tid = threadIdx.x;
    int ocg = tid >> 3, oyl = tid & 7;

    u64 acc[4][8];
#pragma unroll
    for (int o = 0; o < 4; o++)
#pragma unroll
        for (int j = 0; j < 8; j++) acc[o][j] = 0ULL;

    int iy_base = oy0 * 2 - 1, ix_base = ox0 * 2 - 1;

    for (int ic0 = 0; ic0 < DIM; ic0 += 4) {
        __syncthreads();
        for (int i = tid; i < 8192; i += 256) {
            int oc = i >> 6, k = i & 63;
            ws[oc][k] = w[oc * 2048 + ic0 * 16 + k];
        }
        for (int i = tid; i < 4 * 18 * 18; i += 256) {
            int ic = i / 324; int rem = i - ic * 324;
            int r = rem / 18; int c = rem - r * 18;
            int iy = iy_base + r, ix = ix_base + c;
            float v = 0.f;
            if ((unsigned)iy < H1 && (unsigned)ix < H1)
                v = g_h[((n * DIM + ic0 + ic) * H1 + iy) * H1 + ix];
            ins[ic][r][c] = v;
        }
        __syncthreads();
#pragma unroll
        for (int icl = 0; icl < 4; icl++) {
#pragma unroll
            for (int kh = 0; kh < 4; kh++) {
                const float* rp = &ins[icl][oyl * 2 + kh][0];
                u64 ivp[9];
#pragma unroll
                for (int m = 0; m < 9; m++) ivp[m] = lds2(rp + 2 * m);
#pragma unroll
                for (int o = 0; o < 4; o++) {
                    const float* wpt = &ws[ocg * 4 + o][icl * 16 + kh * 4];
                    u64 w01 = lds2(wpt);
                    u64 w23 = lds2(wpt + 2);
#pragma unroll
                    for (int j = 0; j < 8; j++) {
                        fma2(acc[o][j], ivp[j],     w01);
                        fma2(acc[o][j], ivp[j + 1], w23);
                    }
                }
            }
        }
    }
    int oy = oy0 + oyl;
#pragma unroll
    for (int o = 0; o < 4; o++) {
        int oc = ocg * 4 + o;
        float* op = ze + ((n * DIM + oc) * H2 + oy) * H2 + ox0;
#pragma unroll
        for (int j = 0; j < 8; j++) {
            float2 v = unpack2(acc[o][j]);
            op[j] = v.x + v.y;
        }
    }
}

// ---------------------------------------------------------------------------
// VQ: 128 vectors/block, 256 threads, 8 vec x 8 code per thread, f32x2.
// ---------------------------------------------------------------------------
__global__ __launch_bounds__(256) void vq_kernel(
    const float* __restrict__ ze, const float* __restrict__ emb,
    float* __restrict__ zq) {
    extern __shared__ float sm[];
    float* z_s = sm;                  // [128][132]
    float* c_s = sm + 128 * 132;      // [128][132]
    __shared__ int idx_s[128];

    int tid = threadIdx.x;
    int v0 = blockIdx.x * 128;
    int b = v0 >> 12;
    int s0 = v0 & 4095;

    for (int i = tid; i < 4096; i += 256) {
        int d = i >> 5, vl4 = (i & 31) * 4;
        float4 t = *(const float4*)&ze[(b * DIM + d) * 4096 + s0 + vl4];
        *(float4*)&z_s[d * 132 + vl4] = t;
    }

    int vg = tid >> 4, cg = tid & 15;
    float minv[8];
    int mini[8];
#pragma unroll
    for (int v = 0; v < 8; v++) { minv[v] = 3.0e38f; mini[v] = 0; }

    u64 dot[4][8];
#pragma unroll
    for (int vp = 0; vp < 4; vp++)
#pragma unroll
        for (int c = 0; c < 8; c++) dot[vp][c] = 0ULL;

    for (int ch = 0; ch < 4; ch++) {
        __syncthreads();
        int cbase = ch * 128;
        for (int i = tid; i < 4096; i += 256) {
            int cl = i & 127, dq = (i >> 7) * 4;
            float4 t = *(const float4*)&emb[(cbase + cl) * DIM + dq];
            c_s[(dq + 0) * 132 + cl] = t.x;
            c_s[(dq + 1) * 132 + cl] = t.y;
            c_s[(dq + 2) * 132 + cl] = t.z;
            c_s[(dq + 3) * 132 + cl] = t.w;
        }
        __syncthreads();

#pragma unroll 2
        for (int d = 0; d < 128; d++) {
            const float* zp = &z_s[d * 132 + vg * 8];
            float4 z0 = *(const float4*)zp;
            float4 z1 = *(const float4*)(zp + 4);
            u64 zpk[4];
            zpk[0] = pack2(z0.x, z0.y); zpk[1] = pack2(z0.z, z0.w);
            zpk[2] = pack2(z1.x, z1.y); zpk[3] = pack2(z1.z, z1.w);
            const float* cp = &c_s[d * 132];
            float4 c0 = *(const float4*)(cp + cg * 4);
            float4 c1 = *(const float4*)(cp + 64 + cg * 4);
            u64 cb[8];
            cb[0] = pack2(c0.x, c0.x); cb[1] = pack2(c0.y, c0.y);
            cb[2] = pack2(c0.z, c0.z); cb[3] = pack2(c0.w, c0.w);
            cb[4] = pack2(c1.x, c1.x); cb[5] = pack2(c1.y, c1.y);
            cb[6] = pack2(c1.z, c1.z); cb[7] = pack2(c1.w, c1.w);
#pragma unroll
            for (int vp = 0; vp < 4; vp++)
#pragma unroll
                for (int c = 0; c < 8; c++) fma2(dot[vp][c], zpk[vp], cb[c]);
        }

#pragma unroll
        for (int c = 0; c < 8; c++) {
            int code = cbase + (c < 4 ? cg * 4 + c : 64 + cg * 4 + (c - 4));
            float cn = g_cnorm[code];
#pragma unroll
            for (int vp = 0; vp < 4; vp++) {
                float2 dv = unpack2(dot[vp][c]);
                float d0 = fmaf(-2.f, dv.x, cn);
                float d1 = fmaf(-2.f, dv.y, cn);
                if (d0 < minv[2 * vp])     { minv[2 * vp] = d0;     mini[2 * vp] = code; }
                if (d1 < minv[2 * vp + 1]) { minv[2 * vp + 1] = d1; mini[2 * vp + 1] = code; }
                dot[vp][c] = 0ULL;
            }
        }
    }

    __syncthreads();
    float* red_d = c_s;
    int* red_i = (int*)(c_s + 2048);
#pragma unroll
    for (int v = 0; v < 8; v++) {
        int vl = vg * 8 + v;
        red_d[vl * 16 + cg] = minv[v];
        red_i[vl * 16 + cg] = mini[v];
    }
    __syncthreads();
    if (tid < 128) {
        float bd = red_d[tid * 16]; int bi = red_i[tid * 16];
        for (int g = 1; g < 16; g++) {
            float d2 = red_d[tid * 16 + g]; int i2 = red_i[tid * 16 + g];
            if (d2 < bd || (d2 == bd && i2 < bi)) { bd = d2; bi = i2; }
        }
        idx_s[tid] = bi;
    }
    __syncthreads();
    for (int i = tid; i < 16384; i += 256) {
        int d = i >> 7, vl = i & 127;
        zq[(b * DIM + d) * 4096 + s0 + vl] = __ldg(&emb[idx_s[vl] * DIM + d]);
    }
}

// ---------------------------------------------------------------------------
// deconv1: z_q -> g, transposed k4 s2 p1, relu. Tile 8p x 16q, 4 oc/thread.
// Parity-permuted weights: 4 taps of a parity group = one LDS.128.
// Accumulators packed over q-pairs (q, q+2).
// ---------------------------------------------------------------------------
__global__ __launch_bounds__(256) void deconv1_kernel(
    const float* __restrict__ w, const float* __restrict__ zq) {
    __shared__ float ws[DIM][68];
    __shared__ float ins[4][6][12];
    int n = blockIdx.z;
    int q0 = blockIdx.x * 16, p0 = blockIdx.y * 8;
    int tid = threadIdx.x;
    int ocg = tid >> 3, pl = tid & 7;
    int a = pl & 1;
    int r0l = (pl + a) >> 1;
    int rb = p0 / 2 - 1, cb = q0 / 2 - 1;

    u64 acc[4][2][4];
#pragma unroll
    for (int o = 0; o < 4; o++)
#pragma unroll
        for (int qp = 0; qp < 2; qp++)
#pragma unroll
            for (int jp = 0; jp < 4; jp++) acc[o][qp][jp] = 0ULL;

    for (int ic0 = 0; ic0 < DIM; ic0 += 4) {
        __syncthreads();
        for (int i = tid; i < 8192; i += 256) {
            int oc = i >> 6, k = i & 63;
            int icl = k >> 4, kk = k & 15, kh = kk >> 2, kw = kk & 3;
            int slot = icl * 16 + ((kh & 1) * 2 + (kw & 1)) * 4
                     + ((kh >> 1) << 1) + (kw >> 1);
            ws[oc][slot] = w[oc * 2048 + ic0 * 16 + k];
        }
        for (int i = tid; i < 240; i += 256) {
            int ic = i / 60; int rem = i - ic * 60;
            int r = rem / 10, c = rem - r * 10;
            int rr = rb + r, cc = cb + c;
            float v = 0.f;
            if ((unsigned)rr < H2 && (unsigned)cc < H2)
                v = zq[((n * DIM + ic0 + ic) * H2 + rr) * H2 + cc];
            ins[ic][r][c] = v;
        }
        __syncthreads();
#pragma unroll
        for (int icl = 0; icl < 4; icl++) {
            float rin0[10], rin1[10];
#pragma unroll
            for (int m = 0; m < 10; m++) {
                rin0[m] = ins[icl][r0l][m];
                rin1[m] = ins[icl][r0l + 1][m];
            }
            u64 ip0[9], ip1[9];
#pragma unroll
            for (int m = 0; m < 9; m++) {
                ip0[m] = pack2(rin0[m], rin0[m + 1]);
                ip1[m] = pack2(rin1[m], rin1[m + 1]);
            }
#pragma unroll
            for (int o = 0; o < 4; o++) {
                const float* wpt = &ws[ocg * 4 + o][icl * 16 + a * 8];
                float4 wg0 = *(const float4*)(wpt);       // parity (a, b=0)
                float4 wg1 = *(const float4*)(wpt + 4);   // parity (a, b=1)
                u64 b00 = pack2(wg0.x, wg0.x), b01 = pack2(wg0.y, wg0.y);
                u64 b10 = pack2(wg0.z, wg0.z), b11 = pack2(wg0.w, wg0.w);
                u64 c00 = pack2(wg1.x, wg1.x), c01 = pack2(wg1.y, wg1.y);
                u64 c10 = pack2(wg1.z, wg1.z), c11 = pack2(wg1.w, wg1.w);
#pragma unroll
                for (int jp = 0; jp < 4; jp++) {
                    fma2(acc[o][0][jp], ip0[2 * jp + 0], b00);
                    fma2(acc[o][0][jp], ip0[2 * jp + 1], b01);
                    fma2(acc[o][0][jp], ip1[2 * jp + 0], b10);
                    fma2(acc[o][0][jp], ip1[2 * jp + 1], b11);
                    fma2(acc[o][1][jp], ip0[2 * jp + 1], c00);
                    fma2(acc[o][1][jp], ip0[2 * jp + 2], c01);
                    fma2(acc[o][1][jp], ip1[2 * jp + 1], c10);
                    fma2(acc[o][1][jp], ip1[2 * jp + 2], c11);
                }
            }
        }
    }
    int p = p0 + pl;
#pragma unroll
    for (int o = 0; o < 4; o++) {
        int oc = ocg * 4 + o;
        float* op = g_g + ((n * DIM + oc) * H1 + p) * H1 + q0;
#pragma unroll
        for (int qp = 0; qp < 2; qp++)
#pragma unroll
            for (int jp = 0; jp < 4; jp++) {
                float2 v = unpack2(acc[o][qp][jp]);
                op[qp + 4 * jp]     = fmaxf(v.x, 0.f);
                op[qp + 4 * jp + 2] = fmaxf(v.y, 0.f);
            }
    }
}

// ---------------------------------------------------------------------------
// deconv2: g -> recon, transposed k4 s2 p1, tanh. Tile 16p x 32q, thread =
// one q-pair (q, q+2) x 3 oc, f32x2 packed, parity-permuted weights.
// ---------------------------------------------------------------------------
__global__ __launch_bounds__(256) void deconv2_kernel(
    const float* __restrict__ w, float* __restrict__ recon) {
    __shared__ float wsp[CIN][DIM * 16];   // permuted, 24 KB
    __shared__ float ins[8][10][20];
    int n = blockIdx.z;
    int p0 = blockIdx.y * 16, q0 = blockIdx.x * 32;
    int tid = threadIdx.x;
    int pl = tid >> 4, qi = tid & 15;
    int qp = qi & 1, jj = qi >> 1;
    int a = pl & 1;
    int r0l = (pl + a) >> 1;
    int c0l = qp + 2 * jj;
    int rb = p0 / 2 - 1, cb = q0 / 2 - 1;

    for (int i = tid; i < CIN * DIM * 16; i += 256) {
        int oc = i >> 11, rem = i & 2047;
        int ic = rem >> 4, k = rem & 15, kh = k >> 2, kw = k & 3;
        int slot = ic * 16 + ((kh & 1) * 2 + (kw & 1)) * 4
                 + ((kh >> 1) << 1) + (kw >> 1);
        wsp[oc][slot] = w[i];
    }

    u64 acc[3] = {0ULL, 0ULL, 0ULL};
    for (int ic0 = 0; ic0 < DIM; ic0 += 8) {
        __syncthreads();
        for (int i = tid; i < 8 * 10 * 18; i += 256) {
            int ic = i / 180; int rem = i - ic * 180;
            int r = rem / 18, c = rem - r * 18;
            int rr = rb + r, cc = cb + c;
            float v = 0.f;
            if ((unsigned)rr < H1 && (unsigned)cc < H1)
                v = g_g[((n * DIM + ic0 + ic) * H1 + rr) * H1 + cc];
            ins[ic][r][c] = v;
        }
        __syncthreads();
#pragma unroll
        for (int icl = 0; icl < 8; icl++) {
            float t00 = ins[icl][r0l][c0l],     t01 = ins[icl][r0l][c0l + 1];
            float t02 = ins[icl][r0l][c0l + 2];
            float t10 = ins[icl][r0l + 1][c0l], t11 = ins[icl][r0l + 1][c0l + 1];
            float t12 = ins[icl][r0l + 1][c0l + 2];
            u64 i0a = pack2(t00, t01), i0b = pack2(t01, t02);
            u64 i1a = pack2(t10, t11), i1b = pack2(t11, t12);
            int kb = (ic0 + icl) * 16 + (a * 2 + qp) * 4;
#pragma unroll
            for (int o = 0; o < 3; o++) {
                float4 wg = *(const float4*)&wsp[o][kb];
                fma2(acc[o], i0a, pack2(wg.x, wg.x));
                fma2(acc[o], i0b, pack2(wg.y, wg.y));
                fma2(acc[o], i1a, pack2(wg.z, wg.z));
                fma2(acc[o], i1b, pack2(wg.w, wg.w));
            }
        }
    }
    int p = p0 + pl, q = q0 + qp + 4 * jj;
#pragma unroll
    for (int o = 0; o < 3; o++) {
        float2 v = unpack2(acc[o]);
        float* op = recon + ((n * CIN + o) * H0 + p) * H0;
        op[q]     = tanhf(v.x);
        op[q + 2] = tanhf(v.y);
    }
}

// ---------------------------------------------------------------------------
#define VQ_SMEM (2 * 128 * 132 * (int)sizeof(float))   // 135168 B

extern "C" void kernel_launch(void* const* d_in, const int* in_sizes, int n_in,
                              void* d_out, int out_size) {
    const float* x    = (const float*)d_in[0];
    const float* w_e1 = (const float*)d_in[1];
    const float* w_e2 = (const float*)d_in[2];
    const float* emb  = (const float*)d_in[3];
    const float* w_d1 = (const float*)d_in[4];
    const float* w_d2 = (const float*)d_in[5];

    float* out   = (float*)d_out;
    float* recon = out;
    float* ze    = out + OFF_ZE;
    float* zq    = out + OFF_ZQ;

    cudaFuncSetAttribute(vq_kernel, cudaFuncAttributeMaxDynamicSharedMemorySize,
                         VQ_SMEM);

    knorm_kernel<<<2, 256>>>(emb);
    conv1_kernel<<<dim3(H1, B), 256>>>(x, w_e1);
    conv2_kernel<<<dim3(8, 8, B), 256>>>(w_e2, ze);
    vq_kernel<<<512, 256, VQ_SMEM>>>(ze, emb, zq);
    deconv1_kernel<<<dim3(8, 16, B), 256>>>(w_d1, zq);
    deconv2_kernel<<<dim3(8, 16, B), 256>>>(w_d2, recon);
}

// round 6
// speedup vs baseline: 1.8189x; 1.5668x over previous
#include <cuda_runtime.h>
#include <math.h>

#define B 16
#define CIN 3
#define DIM 128
#define KCODES 512
#define H0 256
#define H1 128
#define H2 64
#define OFF_ZE  (B*CIN*H0*H0)
#define OFF_ZQ  (OFF_ZE + B*DIM*H2*H2)

__device__ float g_h[B*DIM*H1*H1];
__device__ float g_g[B*DIM*H1*H1];
__device__ float g_cnorm[KCODES];
__device__ int   g_idx[B*H2*H2];
__device__ float g_T[513*16*128];   // [code][tap][oc], row 512 = zeros

typedef unsigned long long u64;
__device__ __forceinline__ void fma2(u64& d, u64 a, u64 b) {
    asm("fma.rn.f32x2 %0, %1, %2, %0;" : "+l"(d) : "l"(a), "l"(b));
}
__device__ __forceinline__ u64 pack2(float lo, float hi) {
    u64 r; asm("mov.b64 %0, {%1, %2};" : "=l"(r) : "f"(lo), "f"(hi)); return r;
}
__device__ __forceinline__ float2 unpack2(u64 v) {
    float2 r; asm("mov.b64 {%0, %1}, %2;" : "=f"(r.x), "=f"(r.y) : "l"(v)); return r;
}
__device__ __forceinline__ u64 lds2(const float* p) { return *(const u64*)p; }

__global__ void knorm_kernel(const float* __restrict__ emb) {
    int k = blockIdx.x * blockDim.x + threadIdx.x;
    if (k < KCODES) {
        const float* e = emb + k * DIM;
        float s = 0.f;
#pragma unroll 8
        for (int d = 0; d < DIM; d++) s += e[d] * e[d];
        g_cnorm[k] = s;
    }
}

// T[k][tap][oc] = sum_ic emb[k][ic] * w_d1[oc][ic][tap];  row k=512 zeroed
__global__ __launch_bounds__(256) void tmat_kernel(
    const float* __restrict__ emb, const float* __restrict__ wd1) {
    __shared__ float ws[2048];   // [ic*16 + tap] for this oc
    int oc = blockIdx.x, tid = threadIdx.x;
    for (int i = tid; i < 2048; i += 256) ws[i] = wd1[oc * 2048 + i];
    __syncthreads();
    for (int k = tid; k < 513; k += 256) {
        float acc[16];
#pragma unroll
        for (int t = 0; t < 16; t++) acc[t] = 0.f;
        if (k < 512) {
            const float* e = emb + k * DIM;
            for (int ic = 0; ic < 128; ic++) {
                float ev = __ldg(e + ic);
                const float* wp = &ws[ic * 16];
#pragma unroll
                for (int t = 0; t < 16; t++) acc[t] += ev * wp[t];
            }
        }
#pragma unroll
        for (int t = 0; t < 16; t++) g_T[(k * 16 + t) * 128 + oc] = acc[t];
    }
}

// conv1 (f32x2)
__global__ __launch_bounds__(256) void conv1_kernel(
    const float* __restrict__ x, const float* __restrict__ w) {
    __shared__ float ws[DIM * 48];
    __shared__ float ins[CIN][4][260];
    int n = blockIdx.y, oy = blockIdx.x, tid = threadIdx.x;
    for (int i = tid; i < DIM * 48; i += 256) ws[i] = w[i];
    int iyb = oy * 2 - 1;
    for (int i = tid; i < CIN * 4 * 258; i += 256) {
        int ic = i / 1032, rem = i - ic * 1032, r = rem / 258, c = rem - r * 258;
        int iy = iyb + r, ix = c - 1;
        float v = 0.f;
        if ((unsigned)iy < H0 && (unsigned)ix < H0) v = x[((n * CIN + ic) * H0 + iy) * H0 + ix];
        ins[ic][r][c] = v;
    }
    __syncthreads();
    int oc = tid >> 1, half = tid & 1;
    u64 wp[24];
#pragma unroll
    for (int ic = 0; ic < 3; ic++)
#pragma unroll
        for (int kh = 0; kh < 4; kh++) {
            const float* wk = &ws[oc * 48 + ic * 16 + kh * 4];
            wp[(ic * 4 + kh) * 2] = pack2(wk[0], wk[1]);
            wp[(ic * 4 + kh) * 2 + 1] = pack2(wk[2], wk[3]);
        }
    float* outp = g_h + ((n * DIM + oc) * H1 + oy) * H1;
    for (int k = 0; k < 64; k += 2) {
        int oxa = half + 2 * k, oxb = oxa + 2;
        u64 aa = 0, ab = 0;
#pragma unroll
        for (int ic = 0; ic < 3; ic++)
#pragma unroll
            for (int kh = 0; kh < 4; kh++) {
                const float* rp = &ins[ic][kh][0];
                u64 w01 = wp[(ic * 4 + kh) * 2], w23 = wp[(ic * 4 + kh) * 2 + 1];
                fma2(aa, lds2(rp + 2 * oxa), w01); fma2(aa, lds2(rp + 2 * oxa + 2), w23);
                fma2(ab, lds2(rp + 2 * oxb), w01); fma2(ab, lds2(rp + 2 * oxb + 2), w23);
            }
        float2 va = unpack2(aa), vb = unpack2(ab);
        outp[oxa] = fmaxf(va.x + va.y, 0.f);
        outp[oxb] = fmaxf(vb.x + vb.y, 0.f);
    }
}

// conv2 (f32x2, R3-passing version)
__global__ __launch_bounds__(256) void conv2_kernel(
    const float* __restrict__ w, float* __restrict__ ze) {
    __shared__ float ws[DIM][68];
    __shared__ float ins[4][18][22];
    int n = blockIdx.z;
    int oy0 = blockIdx.y * 8, ox0 = blockIdx.x * 8;
    int tid = threadIdx.x, ocg = tid >> 3, oyl = tid & 7;
    u64 acc[4][8];
#pragma unroll
    for (int o = 0; o < 4; o++)
#pragma unroll
        for (int j = 0; j < 8; j++) acc[o][j] = 0;
    int iyb = oy0 * 2 - 1, ixb = ox0 * 2 - 1;
    for (int ic0 = 0; ic0 < DIM; ic0 += 4) {
        __syncthreads();
        for (int i = tid; i < 8192; i += 256) {
            int oc = i >> 6, k = i & 63;
            ws[oc][k] = w[oc * 2048 + ic0 * 16 + k];
        }
        for (int i = tid; i < 4 * 18 * 18; i += 256) {
            int ic = i / 324, rem = i - ic * 324, r = rem / 18, c = rem - r * 18;
            int iy = iyb + r, ix = ixb + c;
            float v = 0.f;
            if ((unsigned)iy < H1 && (unsigned)ix < H1)
                v = g_h[((n * DIM + ic0 + ic) * H1 + iy) * H1 + ix];
            ins[ic][r][c] = v;
        }
        __syncthreads();
#pragma unroll
        for (int icl = 0; icl < 4; icl++) {
#pragma unroll
            for (int kh = 0; kh < 4; kh++) {
                const float* rp = &ins[icl][oyl * 2 + kh][0];
                u64 ivp[9];
#pragma unroll
                for (int m = 0; m < 9; m++) ivp[m] = lds2(rp + 2 * m);
#pragma unroll
                for (int o = 0; o < 4; o++) {
                    const float* wpt = &ws[ocg * 4 + o][icl * 16 + kh * 4];
                    u64 w01 = lds2(wpt), w23 = lds2(wpt + 2);
#pragma unroll
                    for (int j = 0; j < 8; j++) {
                        fma2(acc[o][j], ivp[j], w01);
                        fma2(acc[o][j], ivp[j + 1], w23);
                    }
                }
            }
        }
    }
    int oy = oy0 + oyl;
#pragma unroll
    for (int o = 0; o < 4; o++) {
        float* op = ze + ((n * DIM + ocg * 4 + o) * H2 + oy) * H2 + ox0;
#pragma unroll
        for (int j = 0; j < 8; j++) {
            float2 v = unpack2(acc[o][j]);
            op[j] = v.x + v.y;
        }
    }
}

// VQ (writes idx to g_idx too)
__global__ __launch_bounds__(256) void vq_kernel(
    const float* __restrict__ ze, const float* __restrict__ emb, float* __restrict__ zq) {
    extern __shared__ float sm[];
    float* z_s = sm;
    float* c_s = sm + 128 * 132;
    __shared__ int idx_s[128];
    int tid = threadIdx.x;
    int v0 = blockIdx.x * 128, b = v0 >> 12, s0 = v0 & 4095;
    for (int i = tid; i < 4096; i += 256) {
        int d = i >> 5, vl4 = (i & 31) * 4;
        *(float4*)&z_s[d * 132 + vl4] = *(const float4*)&ze[(b * DIM + d) * 4096 + s0 + vl4];
    }
    int vg = tid >> 4, cg = tid & 15;
    float minv[8]; int mini[8];
#pragma unroll
    for (int v = 0; v < 8; v++) { minv[v] = 3.0e38f; mini[v] = 0; }
    u64 dot[4][8];
#pragma unroll
    for (int vp = 0; vp < 4; vp++)
#pragma unroll
        for (int c = 0; c < 8; c++) dot[vp][c] = 0;
    for (int ch = 0; ch < 4; ch++) {
        __syncthreads();
        int cbase = ch * 128;
        for (int i = tid; i < 4096; i += 256) {
            int cl = i & 127, dq = (i >> 7) * 4;
            float4 t = *(const float4*)&emb[(cbase + cl) * DIM + dq];
            c_s[dq * 132 + cl] = t.x; c_s[(dq + 1) * 132 + cl] = t.y;
            c_s[(dq + 2) * 132 + cl] = t.z; c_s[(dq + 3) * 132 + cl] = t.w;
        }
        __syncthreads();
#pragma unroll 2
        for (int d = 0; d < 128; d++) {
            const float* zp = &z_s[d * 132 + vg * 8];
            float4 z0 = *(const float4*)zp, z1 = *(const float4*)(zp + 4);
            u64 zpk[4] = {pack2(z0.x, z0.y), pack2(z0.z, z0.w), pack2(z1.x, z1.y), pack2(z1.z, z1.w)};
            const float* cp = &c_s[d * 132];
            float4 c0 = *(const float4*)(cp + cg * 4), c1 = *(const float4*)(cp + 64 + cg * 4);
            u64 cb[8] = {pack2(c0.x, c0.x), pack2(c0.y, c0.y), pack2(c0.z, c0.z), pack2(c0.w, c0.w),
                         pack2(c1.x, c1.x), pack2(c1.y, c1.y), pack2(c1.z, c1.z), pack2(c1.w, c1.w)};
#pragma unroll
            for (int vp = 0; vp < 4; vp++)
#pragma unroll
                for (int c = 0; c < 8; c++) fma2(dot[vp][c], zpk[vp], cb[c]);
        }
#pragma unroll
        for (int c = 0; c < 8; c++) {
            int code = cbase + (c < 4 ? cg * 4 + c : 64 + cg * 4 + (c - 4));
            float cn = g_cnorm[code];
#pragma unroll
            for (int vp = 0; vp < 4; vp++) {
                float2 dv = unpack2(dot[vp][c]);
                float d0 = fmaf(-2.f, dv.x, cn), d1 = fmaf(-2.f, dv.y, cn);
                if (d0 < minv[2 * vp]) { minv[2 * vp] = d0; mini[2 * vp] = code; }
                if (d1 < minv[2 * vp + 1]) { minv[2 * vp + 1] = d1; mini[2 * vp + 1] = code; }
                dot[vp][c] = 0;
            }
        }
    }
    __syncthreads();
    float* rd = c_s; int* ri = (int*)(c_s + 2048);
#pragma unroll
    for (int v = 0; v < 8; v++) {
        int vl = vg * 8 + v;
        rd[vl * 16 + cg] = minv[v]; ri[vl * 16 + cg] = mini[v];
    }
    __syncthreads();
    if (tid < 128) {
        float bd = rd[tid * 16]; int bi = ri[tid * 16];
        for (int g = 1; g < 16; g++) {
            float d2 = rd[tid * 16 + g]; int i2 = ri[tid * 16 + g];
            if (d2 < bd || (d2 == bd && i2 < bi)) { bd = d2; bi = i2; }
        }
        idx_s[tid] = bi;
        g_idx[v0 + tid] = bi;
    }
    __syncthreads();
    for (int i = tid; i < 16384; i += 256) {
        int d = i >> 7, vl = i & 127;
        zq[(b * DIM + d) * 4096 + s0 + vl] = __ldg(&emb[idx_s[vl] * DIM + d]);
    }
}

// deconv1 as gather of precomputed T rows. Block: 8p x 32q x 128oc.
// Out (p,q): taps kh in {a,a+2} (a=p&1) map to input rows rlo,rlo+1;
// kw in {b,b+2} (b=q&1) map to cols clo,clo+1. val = sum of 4 T entries.
__global__ __launch_bounds__(256) void deconv1_gather_kernel() {
    __shared__ int sidx[6][18];
    int n = blockIdx.z, p0 = blockIdx.y * 8, q0 = blockIdx.x * 32;
    int tid = threadIdx.x;
    int rb = p0 / 2 - 1, cb = q0 / 2 - 1;
    for (int i = tid; i < 108; i += 256) {
        int r = i / 18, c = i - r * 18;
        int rr = rb + r, cc = cb + c;
        sidx[r][c] = ((unsigned)rr < H2 && (unsigned)cc < H2)
                     ? g_idx[n * 4096 + rr * 64 + cc] : 512;
    }
    __syncthreads();
    int oc = tid & 127, half = tid >> 7;
    const float* Toc = g_T + oc;
#pragma unroll
    for (int s = 0; s < 4; s++) {
        int pl = half * 4 + s, p = p0 + pl;
        int a4 = (p & 1) * 4;
        int rl = (pl + (p & 1)) >> 1;
        const int* r0 = sidx[rl];
        const int* r1 = sidx[rl + 1];
        float* op = g_g + ((n * DIM + oc) * H1 + p) * H1 + q0;
        for (int jj = 0; jj < 32; jj += 4) {
            int cl = jj >> 1;
            int k00 = r0[cl], k01 = r0[cl + 1], k02 = r0[cl + 2], k03 = r0[cl + 3];
            int k10 = r1[cl], k11 = r1[cl + 1], k12 = r1[cl + 2], k13 = r1[cl + 3];
            float4 v;
            v.x = __ldg(&Toc[(k00 * 16 + a4)     * 128]) + __ldg(&Toc[(k01 * 16 + a4 + 2)  * 128])
                + __ldg(&Toc[(k10 * 16 + a4 + 8) * 128]) + __ldg(&Toc[(k11 * 16 + a4 + 10) * 128]);
            v.y = __ldg(&Toc[(k01 * 16 + a4 + 1) * 128]) + __ldg(&Toc[(k02 * 16 + a4 + 3)  * 128])
                + __ldg(&Toc[(k11 * 16 + a4 + 9) * 128]) + __ldg(&Toc[(k12 * 16 + a4 + 11) * 128]);
            v.z = __ldg(&Toc[(k01 * 16 + a4)     * 128]) + __ldg(&Toc[(k02 * 16 + a4 + 2)  * 128])
                + __ldg(&Toc[(k11 * 16 + a4 + 8) * 128]) + __ldg(&Toc[(k12 * 16 + a4 + 10) * 128]);
            v.w = __ldg(&Toc[(k02 * 16 + a4 + 1) * 128]) + __ldg(&Toc[(k03 * 16 + a4 + 3)  * 128])
                + __ldg(&Toc[(k12 * 16 + a4 + 9) * 128]) + __ldg(&Toc[(k13 * 16 + a4 + 11) * 128]);
            v.x = fmaxf(v.x, 0.f); v.y = fmaxf(v.y, 0.f);
            v.z = fmaxf(v.z, 0.f); v.w = fmaxf(v.w, 0.f);
            *(float4*)(op + jj) = v;
        }
    }
}

// deconv2 (unchanged)
__global__ __launch_bounds__(256) void deconv2_kernel(
    const float* __restrict__ w, float* __restrict__ recon) {
    __shared__ float wsp[CIN][DIM * 16];
    __shared__ float ins[8][10][20];
    int n = blockIdx.z;
    int p0 = blockIdx.y * 16, q0 = blockIdx.x * 32;
    int tid = threadIdx.x, pl = tid >> 4, qi = tid & 15;
    int qp = qi & 1, jj = qi >> 1, a = pl & 1;
    int r0l = (pl + a) >> 1, c0l = qp + 2 * jj;
    int rb = p0 / 2 - 1, cb = q0 / 2 - 1;
    for (int i = tid; i < CIN * DIM * 16; i += 256) {
        int oc = i >> 11, rem = i & 2047;
        int ic = rem >> 4, k = rem & 15, kh = k >> 2, kw = k & 3;
        int slot = ic * 16 + ((kh & 1) * 2 + (kw & 1)) * 4 + ((kh >> 1) << 1) + (kw >> 1);
        wsp[oc][slot] = w[i];
    }
    u64 acc[3] = {0, 0, 0};
    for (int ic0 = 0; ic0 < DIM; ic0 += 8) {
        __syncthreads();
        for (int i = tid; i < 1440; i += 256) {
            int ic = i / 180, rem = i - ic * 180, r = rem / 18, c = rem - r * 18;
            int rr = rb + r, cc = cb + c;
            float v = 0.f;
            if ((unsigned)rr < H1 && (unsigned)cc < H1)
                v = g_g[((n * DIM + ic0 + ic) * H1 + rr) * H1 + cc];
            ins[ic][r][c] = v;
        }
        __syncthreads();
#pragma unroll
        for (int icl = 0; icl < 8; icl++) {
            float t00 = ins[icl][r0l][c0l], t01 = ins[icl][r0l][c0l + 1], t02 = ins[icl][r0l][c0l + 2];
            float t10 = ins[icl][r0l + 1][c0l], t11 = ins[icl][r0l + 1][c0l + 1], t12 = ins[icl][r0l + 1][c0l + 2];
            u64 i0a = pack2(t00, t01), i0b = pack2(t01, t02);
            u64 i1a = pack2(t10, t11), i1b = pack2(t11, t12);
            int kb = (ic0 + icl) * 16 + (a * 2 + qp) * 4;
#pragma unroll
            for (int o = 0; o < 3; o++) {
                float4 wg = *(const float4*)&wsp[o][kb];
                fma2(acc[o], i0a, pack2(wg.x, wg.x)); fma2(acc[o], i0b, pack2(wg.y, wg.y));
                fma2(acc[o], i1a, pack2(wg.z, wg.z)); fma2(acc[o], i1b, pack2(wg.w, wg.w));
            }
        }
    }
    int p = p0 + pl, q = q0 + qp + 4 * jj;
#pragma unroll
    for (int o = 0; o < 3; o++) {
        float2 v = unpack2(acc[o]);
        float* op = recon + ((n * CIN + o) * H0 + p) * H0;
        op[q] = tanhf(v.x);
        op[q + 2] = tanhf(v.y);
    }
}

#define VQ_SMEM (2 * 128 * 132 * (int)sizeof(float))

extern "C" void kernel_launch(void* const* d_in, const int* in_sizes, int n_in,
                              void* d_out, int out_size) {
    const float* x    = (const float*)d_in[0];
    const float* w_e1 = (const float*)d_in[1];
    const float* w_e2 = (const float*)d_in[2];
    const float* emb  = (const float*)d_in[3];
    const float* w_d1 = (const float*)d_in[4];
    const float* w_d2 = (const float*)d_in[5];
    float* out = (float*)d_out;
    float* recon = out;
    float* ze = out + OFF_ZE;
    float* zq = out + OFF_ZQ;

    cudaFuncSetAttribute(vq_kernel, cudaFuncAttributeMaxDynamicSharedMemorySize, VQ_SMEM);

    knorm_kernel<<<2, 256>>>(emb);
    tmat_kernel<<<128, 256>>>(emb, w_d1);
    conv1_kernel<<<dim3(H1, B), 256>>>(x, w_e1);
    conv2_kernel<<<dim3(8, 8, B), 256>>>(w_e2, ze);
    vq_kernel<<<512, 256, VQ_SMEM>>>(ze, emb, zq);
    deconv1_gather_kernel<<<dim3(4, 16, B), 256>>>();
    deconv2_kernel<<<dim3(8, 16, B), 256>>>(w_d2, recon);
}

// round 10
// speedup vs baseline: 1.8279x; 1.0049x over previous
#include <cuda_runtime.h>
#include <math.h>

#define B 16
#define CIN 3
#define DIM 128
#define KCODES 512
#define H0 256
#define H1 128
#define H2 64
#define OFF_ZE  (B*CIN*H0*H0)
#define OFF_ZQ  (OFF_ZE + B*DIM*H2*H2)

__device__ float g_h[B*DIM*H1*H1];
__device__ float g_g[B*DIM*H1*H1];
__device__ float g_cnorm[KCODES];
__device__ int   g_idx[B*H2*H2];
__device__ float g_T[513*16*128];

typedef unsigned long long u64;
__device__ __forceinline__ void fma2(u64& d, u64 a, u64 b) {
    asm("fma.rn.f32x2 %0, %1, %2, %0;" : "+l"(d) : "l"(a), "l"(b));
}
__device__ __forceinline__ u64 pack2(float lo, float hi) {
    u64 r; asm("mov.b64 %0, {%1, %2};" : "=l"(r) : "f"(lo), "f"(hi)); return r;
}
__device__ __forceinline__ float2 unpack2(u64 v) {
    float2 r; asm("mov.b64 {%0, %1}, %2;" : "=f"(r.x), "=f"(r.y) : "l"(v)); return r;
}
__device__ __forceinline__ u64 lds2(const float* p) { return *(const u64*)p; }

__global__ void knorm_kernel(const float* __restrict__ emb) {
    int k = blockIdx.x * blockDim.x + threadIdx.x;
    if (k < KCODES) {
        const float* e = emb + k * DIM;
        float s = 0.f;
#pragma unroll 8
        for (int d = 0; d < DIM; d++) s += e[d] * e[d];
        g_cnorm[k] = s;
    }
}

__global__ __launch_bounds__(256) void tmat_kernel(
    const float* __restrict__ emb, const float* __restrict__ wd1) {
    __shared__ float ws[2048];
    int oc = blockIdx.x, tid = threadIdx.x;
    for (int i = tid; i < 2048; i += 256) ws[i] = wd1[oc * 2048 + i];
    __syncthreads();
    for (int k = tid; k < 513; k += 256) {
        float acc[16];
#pragma unroll
        for (int t = 0; t < 16; t++) acc[t] = 0.f;
        if (k < 512) {
            const float* e = emb + k * DIM;
            for (int ic = 0; ic < 128; ic++) {
                float ev = __ldg(e + ic);
                const float* wp = &ws[ic * 16];
#pragma unroll
                for (int t = 0; t < 16; t++) acc[t] += ev * wp[t];
            }
        }
#pragma unroll
        for (int t = 0; t < 16; t++) g_T[(k * 16 + t) * 128 + oc] = acc[t];
    }
}

// conv1 (f32x2, ILP4: four outputs in flight, per-output chain unchanged)
__global__ __launch_bounds__(256) void conv1_kernel(
    const float* __restrict__ x, const float* __restrict__ w) {
    __shared__ float ws[DIM * 48];
    __shared__ float ins[CIN][4][260];
    int n = blockIdx.y, oy = blockIdx.x, tid = threadIdx.x;
    for (int i = tid; i < DIM * 48; i += 256) ws[i] = w[i];
    int iyb = oy * 2 - 1;
    for (int i = tid; i < CIN * 4 * 258; i += 256) {
        int ic = i / 1032, rem = i - ic * 1032, r = rem / 258, c = rem - r * 258;
        int iy = iyb + r, ix = c - 1;
        float v = 0.f;
        if ((unsigned)iy < H0 && (unsigned)ix < H0) v = x[((n * CIN + ic) * H0 + iy) * H0 + ix];
        ins[ic][r][c] = v;
    }
    __syncthreads();
    int oc = tid >> 1, half = tid & 1;
    u64 wp[24];
#pragma unroll
    for (int ic = 0; ic < 3; ic++)
#pragma unroll
        for (int kh = 0; kh < 4; kh++) {
            const float* wk = &ws[oc * 48 + ic * 16 + kh * 4];
            wp[(ic * 4 + kh) * 2] = pack2(wk[0], wk[1]);
            wp[(ic * 4 + kh) * 2 + 1] = pack2(wk[2], wk[3]);
        }
    float* outp = g_h + ((n * DIM + oc) * H1 + oy) * H1;
    for (int k = 0; k < 64; k += 4) {
        int oxa = half + 2 * k;
        u64 a0 = 0, a1 = 0, a2 = 0, a3 = 0;
#pragma unroll
        for (int ic = 0; ic < 3; ic++)
#pragma unroll
            for (int kh = 0; kh < 4; kh++) {
                const float* rp = &ins[ic][kh][2 * oxa];
                u64 w01 = wp[(ic * 4 + kh) * 2], w23 = wp[(ic * 4 + kh) * 2 + 1];
                fma2(a0, lds2(rp),      w01); fma2(a0, lds2(rp + 2),  w23);
                fma2(a1, lds2(rp + 4),  w01); fma2(a1, lds2(rp + 6),  w23);
                fma2(a2, lds2(rp + 8),  w01); fma2(a2, lds2(rp + 10), w23);
                fma2(a3, lds2(rp + 12), w01); fma2(a3, lds2(rp + 14), w23);
            }
        float2 v0 = unpack2(a0), v1 = unpack2(a1), v2 = unpack2(a2), v3 = unpack2(a3);
        outp[oxa]     = fmaxf(v0.x + v0.y, 0.f);
        outp[oxa + 2] = fmaxf(v1.x + v1.y, 0.f);
        outp[oxa + 4] = fmaxf(v2.x + v2.y, 0.f);
        outp[oxa + 6] = fmaxf(v3.x + v3.y, 0.f);
    }
}

// conv2 (f32x2, EXACT R6 numerics — do not touch ordering)
__global__ __launch_bounds__(256) void conv2_kernel(
    const float* __restrict__ w, float* __restrict__ ze) {
    __shared__ float ws[DIM][68];
    __shared__ float ins[4][18][22];
    int n = blockIdx.z;
    int oy0 = blockIdx.y * 8, ox0 = blockIdx.x * 8;
    int tid = threadIdx.x, ocg = tid >> 3, oyl = tid & 7;
    u64 acc[4][8];
#pragma unroll
    for (int o = 0; o < 4; o++)
#pragma unroll
        for (int j = 0; j < 8; j++) acc[o][j] = 0;
    int iyb = oy0 * 2 - 1, ixb = ox0 * 2 - 1;
    for (int ic0 = 0; ic0 < DIM; ic0 += 4) {
        __syncthreads();
        for (int i = tid; i < 8192; i += 256) {
            int oc = i >> 6, k = i & 63;
            ws[oc][k] = w[oc * 2048 + ic0 * 16 + k];
        }
        for (int i = tid; i < 4 * 18 * 18; i += 256) {
            int ic = i / 324, rem = i - ic * 324, r = rem / 18, c = rem - r * 18;
            int iy = iyb + r, ix = ixb + c;
            float v = 0.f;
            if ((unsigned)iy < H1 && (unsigned)ix < H1)
                v = g_h[((n * DIM + ic0 + ic) * H1 + iy) * H1 + ix];
            ins[ic][r][c] = v;
        }
        __syncthreads();
#pragma unroll
        for (int icl = 0; icl < 4; icl++) {
#pragma unroll
            for (int kh = 0; kh < 4; kh++) {
                const float* rp = &ins[icl][oyl * 2 + kh][0];
                u64 ivp[9];
#pragma unroll
                for (int m = 0; m < 9; m++) ivp[m] = lds2(rp + 2 * m);
#pragma unroll
                for (int o = 0; o < 4; o++) {
                    const float* wpt = &ws[ocg * 4 + o][icl * 16 + kh * 4];
                    u64 w01 = lds2(wpt), w23 = lds2(wpt + 2);
#pragma unroll
                    for (int j = 0; j < 8; j++) {
                        fma2(acc[o][j], ivp[j], w01);
                        fma2(acc[o][j], ivp[j + 1], w23);
                    }
                }
            }
        }
    }
    int oy = oy0 + oyl;
#pragma unroll
    for (int o = 0; o < 4; o++) {
        float* op = ze + ((n * DIM + ocg * 4 + o) * H2 + oy) * H2 + ox0;
#pragma unroll
        for (int j = 0; j < 8; j++) {
            float2 v = unpack2(acc[o][j]);
            op[j] = v.x + v.y;
        }
    }
}

// VQ: 64 vectors/block (occ 2), same per-dot/compare order as passing version.
__global__ __launch_bounds__(256) void vq_kernel(
    const float* __restrict__ ze, const float* __restrict__ emb, float* __restrict__ zq) {
    extern __shared__ float sm[];
    float* z_s = sm;                 // [128][68]
    float* c_s = sm + 128 * 68;      // [128][132]
    __shared__ int idx_s[64];
    int tid = threadIdx.x;
    int v0 = blockIdx.x * 64, b = v0 >> 12, s0 = v0 & 4095;
    for (int i = tid; i < 2048; i += 256) {
        int d = i >> 4, vl4 = (i & 15) * 4;
        *(float4*)&z_s[d * 68 + vl4] = *(const float4*)&ze[(b * DIM + d) * 4096 + s0 + vl4];
    }
    int vg = tid >> 4, cg = tid & 15;
    float minv[4]; int mini[4];
#pragma unroll
    for (int v = 0; v < 4; v++) { minv[v] = 3.0e38f; mini[v] = 0; }
    u64 dot[2][8];
#pragma unroll
    for (int vp = 0; vp < 2; vp++)
#pragma unroll
        for (int c = 0; c < 8; c++) dot[vp][c] = 0;
    for (int ch = 0; ch < 4; ch++) {
        __syncthreads();
        int cbase = ch * 128;
        for (int i = tid; i < 4096; i += 256) {
            int cl = i & 127, dq = (i >> 7) * 4;
            float4 t = *(const float4*)&emb[(cbase + cl) * DIM + dq];
            c_s[dq * 132 + cl] = t.x; c_s[(dq + 1) * 132 + cl] = t.y;
            c_s[(dq + 2) * 132 + cl] = t.z; c_s[(dq + 3) * 132 + cl] = t.w;
        }
        __syncthreads();
#pragma unroll 2
        for (int d = 0; d < 128; d++) {
            const float* zp = &z_s[d * 68 + vg * 4];
            float4 z0 = *(const float4*)zp;
            u64 zpk[2] = {pack2(z0.x, z0.y), pack2(z0.z, z0.w)};
            const float* cp = &c_s[d * 132];
            float4 c0 = *(const float4*)(cp + cg * 4), c1 = *(const float4*)(cp + 64 + cg * 4);
            u64 cb[8] = {pack2(c0.x, c0.x), pack2(c0.y, c0.y), pack2(c0.z, c0.z), pack2(c0.w, c0.w),
                         pack2(c1.x, c1.x), pack2(c1.y, c1.y), pack2(c1.z, c1.z), pack2(c1.w, c1.w)};
#pragma unroll
            for (int vp = 0; vp < 2; vp++)
#pragma unroll
                for (int c = 0; c < 8; c++) fma2(dot[vp][c], zpk[vp], cb[c]);
        }
#pragma unroll
        for (int c = 0; c < 8; c++) {
            int code = cbase + (c < 4 ? cg * 4 + c : 64 + cg * 4 + (c - 4));
            float cn = g_cnorm[code];
#pragma unroll
            for (int vp = 0; vp < 2; vp++) {
                float2 dv = unpack2(dot[vp][c]);
                float d0 = fmaf(-2.f, dv.x, cn), d1 = fmaf(-2.f, dv.y, cn);
                if (d0 < minv[2 * vp]) { minv[2 * vp] = d0; mini[2 * vp] = code; }
                if (d1 < minv[2 * vp + 1]) { minv[2 * vp + 1] = d1; mini[2 * vp + 1] = code; }
                dot[vp][c] = 0;
            }
        }
    }
    __syncthreads();
    float* rd = c_s; int* ri = (int*)(c_s + 1024);
#pragma unroll
    for (int v = 0; v < 4; v++) {
        int vl = vg * 4 + v;
        rd[vl * 16 + cg] = minv[v]; ri[vl * 16 + cg] = mini[v];
    }
    __syncthreads();
    if (tid < 64) {
        float bd = rd[tid * 16]; int bi = ri[tid * 16];
        for (int g = 1; g < 16; g++) {
            float d2 = rd[tid * 16 + g]; int i2 = ri[tid * 16 + g];
            if (d2 < bd || (d2 == bd && i2 < bi)) { bd = d2; bi = i2; }
        }
        idx_s[tid] = bi;
        g_idx[v0 + tid] = bi;
    }
    __syncthreads();
    for (int i = tid; i < 8192; i += 256) {
        int d = i >> 6, vl = i & 63;
        zq[(b * DIM + d) * 4096 + s0 + vl] = __ldg(&emb[idx_s[vl] * DIM + d]);
    }
}

// deconv1 gather (unchanged)
__global__ __launch_bounds__(256) void deconv1_gather_kernel() {
    __shared__ int sidx[6][18];
    int n = blockIdx.z, p0 = blockIdx.y * 8, q0 = blockIdx.x * 32;
    int tid = threadIdx.x;
    int rb = p0 / 2 - 1, cb = q0 / 2 - 1;
    for (int i = tid; i < 108; i += 256) {
        int r = i / 18, c = i - r * 18;
        int rr = rb + r, cc = cb + c;
        sidx[r][c] = ((unsigned)rr < H2 && (unsigned)cc < H2)
                     ? g_idx[n * 4096 + rr * 64 + cc] : 512;
    }
    __syncthreads();
    int oc = tid & 127, half = tid >> 7;
    const float* Toc = g_T + oc;
#pragma unroll
    for (int s = 0; s < 4; s++) {
        int pl = half * 4 + s, p = p0 + pl;
        int a4 = (p & 1) * 4;
        int rl = (pl + (p & 1)) >> 1;
        const int* r0 = sidx[rl];
        const int* r1 = sidx[rl + 1];
        float* op = g_g + ((n * DIM + oc) * H1 + p) * H1 + q0;
        for (int jj = 0; jj < 32; jj += 4) {
            int cl = jj >> 1;
            int k00 = r0[cl], k01 = r0[cl + 1], k02 = r0[cl + 2], k03 = r0[cl + 3];
            int k10 = r1[cl], k11 = r1[cl + 1], k12 = r1[cl + 2], k13 = r1[cl + 3];
            float4 v;
            v.x = __ldg(&Toc[(k00 * 16 + a4)     * 128]) + __ldg(&Toc[(k01 * 16 + a4 + 2)  * 128])
                + __ldg(&Toc[(k10 * 16 + a4 + 8) * 128]) + __ldg(&Toc[(k11 * 16 + a4 + 10) * 128]);
            v.y = __ldg(&Toc[(k01 * 16 + a4 + 1) * 128]) + __ldg(&Toc[(k02 * 16 + a4 + 3)  * 128])
                + __ldg(&Toc[(k11 * 16 + a4 + 9) * 128]) + __ldg(&Toc[(k12 * 16 + a4 + 11) * 128]);
            v.z = __ldg(&Toc[(k01 * 16 + a4)     * 128]) + __ldg(&Toc[(k02 * 16 + a4 + 2)  * 128])
                + __ldg(&Toc[(k11 * 16 + a4 + 8) * 128]) + __ldg(&Toc[(k12 * 16 + a4 + 10) * 128]);
            v.w = __ldg(&Toc[(k02 * 16 + a4 + 1) * 128]) + __ldg(&Toc[(k03 * 16 + a4 + 3)  * 128])
                + __ldg(&Toc[(k12 * 16 + a4 + 9) * 128]) + __ldg(&Toc[(k13 * 16 + a4 + 11) * 128]);
            v.x = fmaxf(v.x, 0.f); v.y = fmaxf(v.y, 0.f);
            v.z = fmaxf(v.z, 0.f); v.w = fmaxf(v.w, 0.f);
            *(float4*)(op + jj) = v;
        }
    }
}

// deconv2 (unchanged)
__global__ __launch_bounds__(256) void deconv2_kernel(
    const float* __restrict__ w, float* __restrict__ recon) {
    __shared__ float wsp[CIN][DIM * 16];
    __shared__ float ins[8][10][20];
    int n = blockIdx.z;
    int p0 = blockIdx.y * 16, q0 = blockIdx.x * 32;
    int tid = threadIdx.x, pl = tid >> 4, qi = tid & 15;
    int qp = qi & 1, jj = qi >> 1, a = pl & 1;
    int r0l = (pl + a) >> 1, c0l = qp + 2 * jj;
    int rb = p0 / 2 - 1, cb = q0 / 2 - 1;
    for (int i = tid; i < CIN * DIM * 16; i += 256) {
        int oc = i >> 11, rem = i & 2047;
        int ic = rem >> 4, k = rem & 15, kh = k >> 2, kw = k & 3;
        int slot = ic * 16 + ((kh & 1) * 2 + (kw & 1)) * 4 + ((kh >> 1) << 1) + (kw >> 1);
        wsp[oc][slot] = w[i];
    }
    u64 acc[3] = {0, 0, 0};
    for (int ic0 = 0; ic0 < DIM; ic0 += 8) {
        __syncthreads();
        for (int i = tid; i < 1440; i += 256) {
            int ic = i / 180, rem = i - ic * 180, r = rem / 18, c = rem - r * 18;
            int rr = rb + r, cc = cb + c;
            float v = 0.f;
            if ((unsigned)rr < H1 && (unsigned)cc < H1)
                v = g_g[((n * DIM + ic0 + ic) * H1 + rr) * H1 + cc];
            ins[ic][r][c] = v;
        }
        __syncthreads();
#pragma unroll
        for (int icl = 0; icl < 8; icl++) {
            float t00 = ins[icl][r0l][c0l], t01 = ins[icl][r0l][c0l + 1], t02 = ins[icl][r0l][c0l + 2];
            float t10 = ins[icl][r0l + 1][c0l], t11 = ins[icl][r0l + 1][c0l + 1], t12 = ins[icl][r0l + 1][c0l + 2];
            u64 i0a = pack2(t00, t01), i0b = pack2(t01, t02);
            u64 i1a = pack2(t10, t11), i1b = pack2(t11, t12);
            int kb = (ic0 + icl) * 16 + (a * 2 + qp) * 4;
#pragma unroll
            for (int o = 0; o < 3; o++) {
                float4 wg = *(const float4*)&wsp[o][kb];
                fma2(acc[o], i0a, pack2(wg.x, wg.x)); fma2(acc[o], i0b, pack2(wg.y, wg.y));
                fma2(acc[o], i1a, pack2(wg.z, wg.z)); fma2(acc[o], i1b, pack2(wg.w, wg.w));
            }
        }
    }
    int p = p0 + pl, q = q0 + qp + 4 * jj;
#pragma unroll
    for (int o = 0; o < 3; o++) {
        float2 v = unpack2(acc[o]);
        float* op = recon + ((n * CIN + o) * H0 + p) * H0;
        op[q] = tanhf(v.x);
        op[q + 2] = tanhf(v.y);
    }
}

#define VQ_SMEM ((128 * 68 + 128 * 132) * (int)sizeof(float))   // 102400

extern "C" void kernel_launch(void* const* d_in, const int* in_sizes, int n_in,
                              void* d_out, int out_size) {
    const float* x    = (const float*)d_in[0];
    const float* w_e1 = (const float*)d_in[1];
    const float* w_e2 = (const float*)d_in[2];
    const float* emb  = (const float*)d_in[3];
    const float* w_d1 = (const float*)d_in[4];
    const float* w_d2 = (const float*)d_in[5];
    float* out = (float*)d_out;
    float* recon = out;
    float* ze = out + OFF_ZE;
    float* zq = out + OFF_ZQ;

    cudaFuncSetAttribute(vq_kernel, cudaFuncAttributeMaxDynamicSharedMemorySize, VQ_SMEM);

    knorm_kernel<<<2, 256>>>(emb);
    tmat_kernel<<<128, 256>>>(emb, w_d1);
    conv1_kernel<<<dim3(H1, B), 256>>>(x, w_e1);
    conv2_kernel<<<dim3(8, 8, B), 256>>>(w_e2, ze);
    vq_kernel<<<1024, 256, VQ_SMEM>>>(ze, emb, zq);
    deconv1_gather_kernel<<<dim3(4, 16, B), 256>>>();
    deconv2_kernel<<<dim3(8, 16, B), 256>>>(w_d2, recon);
}

// round 11
// speedup vs baseline: 2.2056x; 1.2067x over previous
#include <cuda_runtime.h>
#include <math.h>

#define B 16
#define CIN 3
#define DIM 128
#define KCODES 512
#define H0 256
#define H1 128
#define H2 64
#define OFF_ZE  (B*CIN*H0*H0)
#define OFF_ZQ  (OFF_ZE + B*DIM*H2*H2)

__device__ float g_h[B*DIM*H1*H1];
__device__ float g_g[B*DIM*H1*H1];
__device__ float g_cnorm[KCODES];
__device__ int   g_idx[B*H2*H2];
__device__ float g_T[513*16*128];

typedef unsigned long long u64;
typedef unsigned int u32;
__device__ __forceinline__ void fma2(u64& d, u64 a, u64 b) {
    asm("fma.rn.f32x2 %0, %1, %2, %0;" : "+l"(d) : "l"(a), "l"(b));
}
__device__ __forceinline__ u64 pack2(float lo, float hi) {
    u64 r; asm("mov.b64 %0, {%1, %2};" : "=l"(r) : "f"(lo), "f"(hi)); return r;
}
__device__ __forceinline__ float2 unpack2(u64 v) {
    float2 r; asm("mov.b64 {%0, %1}, %2;" : "=f"(r.x), "=f"(r.y) : "l"(v)); return r;
}
__device__ __forceinline__ u64 lds2(const float* p) { return *(const u64*)p; }
__device__ __forceinline__ u32 cvta_s(const void* p) {
    u32 a; asm("{.reg .u64 t; cvta.to.shared.u64 t, %1; cvt.u32.u64 %0, t;}" : "=r"(a) : "l"(p));
    return a;
}
__device__ __forceinline__ void cp16(u32 d, const void* s) {
    asm volatile("cp.async.ca.shared.global [%0], [%1], 16;" :: "r"(d), "l"(s));
}
__device__ __forceinline__ void cp4z(u32 d, const void* s, int sz) {
    asm volatile("cp.async.ca.shared.global [%0], [%1], 4, %2;" :: "r"(d), "l"(s), "r"(sz));
}
#define CP_COMMIT() asm volatile("cp.async.commit_group;" ::: "memory")
#define CP_WAIT0()  asm volatile("cp.async.wait_group 0;" ::: "memory")

__global__ void knorm_kernel(const float* __restrict__ emb) {
    int k = blockIdx.x * blockDim.x + threadIdx.x;
    if (k < KCODES) {
        const float* e = emb + k * DIM;
        float s = 0.f;
#pragma unroll 8
        for (int d = 0; d < DIM; d++) s += e[d] * e[d];
        g_cnorm[k] = s;
    }
}

__global__ __launch_bounds__(256) void tmat_kernel(
    const float* __restrict__ emb, const float* __restrict__ wd1) {
    __shared__ float ws[2048];
    int oc = blockIdx.x, tid = threadIdx.x;
    for (int i = tid; i < 2048; i += 256) ws[i] = wd1[oc * 2048 + i];
    __syncthreads();
    for (int k = tid; k < 513; k += 256) {
        float acc[16];
#pragma unroll
        for (int t = 0; t < 16; t++) acc[t] = 0.f;
        if (k < 512) {
            const float* e = emb + k * DIM;
            for (int ic = 0; ic < 128; ic++) {
                float ev = __ldg(e + ic);
                const float* wp = &ws[ic * 16];
#pragma unroll
                for (int t = 0; t < 16; t++) acc[t] += ev * wp[t];
            }
        }
#pragma unroll
        for (int t = 0; t < 16; t++) g_T[(k * 16 + t) * 128 + oc] = acc[t];
    }
}

// conv1 (f32x2 ILP4, unchanged from R10)
__global__ __launch_bounds__(256) void conv1_kernel(
    const float* __restrict__ x, const float* __restrict__ w) {
    __shared__ float ws[DIM * 48];
    __shared__ float ins[CIN][4][260];
    int n = blockIdx.y, oy = blockIdx.x, tid = threadIdx.x;
    for (int i = tid; i < DIM * 48; i += 256) ws[i] = w[i];
    int iyb = oy * 2 - 1;
    for (int i = tid; i < CIN * 4 * 258; i += 256) {
        int ic = i / 1032, rem = i - ic * 1032, r = rem / 258, c = rem - r * 258;
        int iy = iyb + r, ix = c - 1;
        float v = 0.f;
        if ((unsigned)iy < H0 && (unsigned)ix < H0) v = x[((n * CIN + ic) * H0 + iy) * H0 + ix];
        ins[ic][r][c] = v;
    }
    __syncthreads();
    int oc = tid >> 1, half = tid & 1;
    u64 wp[24];
#pragma unroll
    for (int ic = 0; ic < 3; ic++)
#pragma unroll
        for (int kh = 0; kh < 4; kh++) {
            const float* wk = &ws[oc * 48 + ic * 16 + kh * 4];
            wp[(ic * 4 + kh) * 2] = pack2(wk[0], wk[1]);
            wp[(ic * 4 + kh) * 2 + 1] = pack2(wk[2], wk[3]);
        }
    float* outp = g_h + ((n * DIM + oc) * H1 + oy) * H1;
    for (int k = 0; k < 64; k += 4) {
        int oxa = half + 2 * k;
        u64 a0 = 0, a1 = 0, a2 = 0, a3 = 0;
#pragma unroll
        for (int ic = 0; ic < 3; ic++)
#pragma unroll
            for (int kh = 0; kh < 4; kh++) {
                const float* rp = &ins[ic][kh][2 * oxa];
                u64 w01 = wp[(ic * 4 + kh) * 2], w23 = wp[(ic * 4 + kh) * 2 + 1];
                fma2(a0, lds2(rp),      w01); fma2(a0, lds2(rp + 2),  w23);
                fma2(a1, lds2(rp + 4),  w01); fma2(a1, lds2(rp + 6),  w23);
                fma2(a2, lds2(rp + 8),  w01); fma2(a2, lds2(rp + 10), w23);
                fma2(a3, lds2(rp + 12), w01); fma2(a3, lds2(rp + 14), w23);
            }
        float2 v0 = unpack2(a0), v1 = unpack2(a1), v2 = unpack2(a2), v3 = unpack2(a3);
        outp[oxa]     = fmaxf(v0.x + v0.y, 0.f);
        outp[oxa + 2] = fmaxf(v1.x + v1.y, 0.f);
        outp[oxa + 4] = fmaxf(v2.x + v2.y, 0.f);
        outp[oxa + 6] = fmaxf(v3.x + v3.y, 0.f);
    }
}

// conv2: same FMA chains (bitwise) + cp.async double-buffered staging.
#define C2_WS_F  8704            // 128*68
#define C2_BUF_F (C2_WS_F + 1584)  // + 4*18*22 = 10288 floats
#define C2_SMEM  (2 * C2_BUF_F * 4)

__device__ __forceinline__ void c2_prefetch(int tid, int n, int iyb, int ixb,
                                            int st, float* buf,
                                            const float* __restrict__ w) {
    int ic0 = st * 4;
#pragma unroll 2
    for (int i = tid; i < 2048; i += 256) {
        int oc = i >> 4, k4 = (i & 15) * 4;
        cp16(cvta_s(buf + oc * 68 + k4), w + oc * 2048 + ic0 * 16 + k4);
    }
    float* insb = buf + C2_WS_F;
#pragma unroll 2
    for (int i = tid; i < 1296; i += 256) {
        int ic = i / 324, rem = i - ic * 324, r = rem / 18, c = rem - r * 18;
        int iy = iyb + r, ix = ixb + c;
        bool ok = ((unsigned)iy < H1) && ((unsigned)ix < H1);
        const float* src = ok ? &g_h[((n * DIM + ic0 + ic) * H1 + iy) * H1 + ix] : g_h;
        cp4z(cvta_s(insb + ic * 396 + r * 22 + c), src, ok ? 4 : 0);
    }
}

__global__ __launch_bounds__(256, 2) void conv2_kernel(
    const float* __restrict__ w, float* __restrict__ ze) {
    extern __shared__ float s2[];
    int n = blockIdx.z;
    int oy0 = blockIdx.y * 8, ox0 = blockIdx.x * 8;
    int tid = threadIdx.x, ocg = tid >> 3, oyl = tid & 7;
    int iyb = oy0 * 2 - 1, ixb = ox0 * 2 - 1;
    u64 acc[4][8];
#pragma unroll
    for (int o = 0; o < 4; o++)
#pragma unroll
        for (int j = 0; j < 8; j++) acc[o][j] = 0;

    c2_prefetch(tid, n, iyb, ixb, 0, s2, w);
    CP_COMMIT();
    for (int st = 0; st < 32; st++) {
        CP_WAIT0();
        __syncthreads();
        if (st < 31) {
            c2_prefetch(tid, n, iyb, ixb, st + 1, s2 + ((st + 1) & 1) * C2_BUF_F, w);
            CP_COMMIT();
        }
        float* wsb = s2 + (st & 1) * C2_BUF_F;
        float* insb = wsb + C2_WS_F;
#pragma unroll
        for (int icl = 0; icl < 4; icl++) {
#pragma unroll
            for (int kh = 0; kh < 4; kh++) {
                const float* rp = insb + icl * 396 + (oyl * 2 + kh) * 22;
                u64 ivp[9];
#pragma unroll
                for (int m = 0; m < 9; m++) ivp[m] = lds2(rp + 2 * m);
#pragma unroll
                for (int o = 0; o < 4; o++) {
                    const float* wpt = wsb + (ocg * 4 + o) * 68 + icl * 16 + kh * 4;
                    u64 w01 = lds2(wpt), w23 = lds2(wpt + 2);
#pragma unroll
                    for (int j = 0; j < 8; j++) {
                        fma2(acc[o][j], ivp[j], w01);
                        fma2(acc[o][j], ivp[j + 1], w23);
                    }
                }
            }
        }
    }
    int oy = oy0 + oyl;
#pragma unroll
    for (int o = 0; o < 4; o++) {
        float* op = ze + ((n * DIM + ocg * 4 + o) * H2 + oy) * H2 + ox0;
#pragma unroll
        for (int j = 0; j < 8; j++) {
            float2 v = unpack2(acc[o][j]);
            op[j] = v.x + v.y;
        }
    }
}

// VQ (occ-2 version from R10, unchanged)
__global__ __launch_bounds__(256) void vq_kernel(
    const float* __restrict__ ze, const float* __restrict__ emb, float* __restrict__ zq) {
    extern __shared__ float sm[];
    float* z_s = sm;
    float* c_s = sm + 128 * 68;
    __shared__ int idx_s[64];
    int tid = threadIdx.x;
    int v0 = blockIdx.x * 64, b = v0 >> 12, s0 = v0 & 4095;
    for (int i = tid; i < 2048; i += 256) {
        int d = i >> 4, vl4 = (i & 15) * 4;
        *(float4*)&z_s[d * 68 + vl4] = *(const float4*)&ze[(b * DIM + d) * 4096 + s0 + vl4];
    }
    int vg = tid >> 4, cg = tid & 15;
    float minv[4]; int mini[4];
#pragma unroll
    for (int v = 0; v < 4; v++) { minv[v] = 3.0e38f; mini[v] = 0; }
    u64 dot[2][8];
#pragma unroll
    for (int vp = 0; vp < 2; vp++)
#pragma unroll
        for (int c = 0; c < 8; c++) dot[vp][c] = 0;
    for (int ch = 0; ch < 4; ch++) {
        __syncthreads();
        int cbase = ch * 128;
        for (int i = tid; i < 4096; i += 256) {
            int cl = i & 127, dq = (i >> 7) * 4;
            float4 t = *(const float4*)&emb[(cbase + cl) * DIM + dq];
            c_s[dq * 132 + cl] = t.x; c_s[(dq + 1) * 132 + cl] = t.y;
            c_s[(dq + 2) * 132 + cl] = t.z; c_s[(dq + 3) * 132 + cl] = t.w;
        }
        __syncthreads();
#pragma unroll 2
        for (int d = 0; d < 128; d++) {
            const float* zp = &z_s[d * 68 + vg * 4];
            float4 z0 = *(const float4*)zp;
            u64 zpk[2] = {pack2(z0.x, z0.y), pack2(z0.z, z0.w)};
            const float* cp = &c_s[d * 132];
            float4 c0 = *(const float4*)(cp + cg * 4), c1 = *(const float4*)(cp + 64 + cg * 4);
            u64 cb[8] = {pack2(c0.x, c0.x), pack2(c0.y, c0.y), pack2(c0.z, c0.z), pack2(c0.w, c0.w),
                         pack2(c1.x, c1.x), pack2(c1.y, c1.y), pack2(c1.z, c1.z), pack2(c1.w, c1.w)};
#pragma unroll
            for (int vp = 0; vp < 2; vp++)
#pragma unroll
                for (int c = 0; c < 8; c++) fma2(dot[vp][c], zpk[vp], cb[c]);
        }
#pragma unroll
        for (int c = 0; c < 8; c++) {
            int code = cbase + (c < 4 ? cg * 4 + c : 64 + cg * 4 + (c - 4));
            float cn = g_cnorm[code];
#pragma unroll
            for (int vp = 0; vp < 2; vp++) {
                float2 dv = unpack2(dot[vp][c]);
                float d0 = fmaf(-2.f, dv.x, cn), d1 = fmaf(-2.f, dv.y, cn);
                if (d0 < minv[2 * vp]) { minv[2 * vp] = d0; mini[2 * vp] = code; }
                if (d1 < minv[2 * vp + 1]) { minv[2 * vp + 1] = d1; mini[2 * vp + 1] = code; }
                dot[vp][c] = 0;
            }
        }
    }
    __syncthreads();
    float* rd = c_s; int* ri = (int*)(c_s + 1024);
#pragma unroll
    for (int v = 0; v < 4; v++) {
        int vl = vg * 4 + v;
        rd[vl * 16 + cg] = minv[v]; ri[vl * 16 + cg] = mini[v];
    }
    __syncthreads();
    if (tid < 64) {
        float bd = rd[tid * 16]; int bi = ri[tid * 16];
        for (int g = 1; g < 16; g++) {
            float d2 = rd[tid * 16 + g]; int i2 = ri[tid * 16 + g];
            if (d2 < bd || (d2 == bd && i2 < bi)) { bd = d2; bi = i2; }
        }
        idx_s[tid] = bi;
        g_idx[v0 + tid] = bi;
    }
    __syncthreads();
    for (int i = tid; i < 8192; i += 256) {
        int d = i >> 6, vl = i & 63;
        zq[(b * DIM + d) * 4096 + s0 + vl] = __ldg(&emb[idx_s[vl] * DIM + d]);
    }
}

// deconv1 gather (unchanged)
__global__ __launch_bounds__(256) void deconv1_gather_kernel() {
    __shared__ int sidx[6][18];
    int n = blockIdx.z, p0 = blockIdx.y * 8, q0 = blockIdx.x * 32;
    int tid = threadIdx.x;
    int rb = p0 / 2 - 1, cb = q0 / 2 - 1;
    for (int i = tid; i < 108; i += 256) {
        int r = i / 18, c = i - r * 18;
        int rr = rb + r, cc = cb + c;
        sidx[r][c] = ((unsigned)rr < H2 && (unsigned)cc < H2)
                     ? g_idx[n * 4096 + rr * 64 + cc] : 512;
    }
    __syncthreads();
    int oc = tid & 127, half = tid >> 7;
    const float* Toc = g_T + oc;
#pragma unroll
    for (int s = 0; s < 4; s++) {
        int pl = half * 4 + s, p = p0 + pl;
        int a4 = (p & 1) * 4;
        int rl = (pl + (p & 1)) >> 1;
        const int* r0 = sidx[rl];
        const int* r1 = sidx[rl + 1];
        float* op = g_g + ((n * DIM + oc) * H1 + p) * H1 + q0;
        for (int jj = 0; jj < 32; jj += 4) {
            int cl = jj >> 1;
            int k00 = r0[cl], k01 = r0[cl + 1], k02 = r0[cl + 2], k03 = r0[cl + 3];
            int k10 = r1[cl], k11 = r1[cl + 1], k12 = r1[cl + 2], k13 = r1[cl + 3];
            float4 v;
            v.x = __ldg(&Toc[(k00 * 16 + a4)     * 128]) + __ldg(&Toc[(k01 * 16 + a4 + 2)  * 128])
                + __ldg(&Toc[(k10 * 16 + a4 + 8) * 128]) + __ldg(&Toc[(k11 * 16 + a4 + 10) * 128]);
            v.y = __ldg(&Toc[(k01 * 16 + a4 + 1) * 128]) + __ldg(&Toc[(k02 * 16 + a4 + 3)  * 128])
                + __ldg(&Toc[(k11 * 16 + a4 + 9) * 128]) + __ldg(&Toc[(k12 * 16 + a4 + 11) * 128]);
            v.z = __ldg(&Toc[(k01 * 16 + a4)     * 128]) + __ldg(&Toc[(k02 * 16 + a4 + 2)  * 128])
                + __ldg(&Toc[(k11 * 16 + a4 + 8) * 128]) + __ldg(&Toc[(k12 * 16 + a4 + 10) * 128]);
            v.w = __ldg(&Toc[(k02 * 16 + a4 + 1) * 128]) + __ldg(&Toc[(k03 * 16 + a4 + 3)  * 128])
                + __ldg(&Toc[(k12 * 16 + a4 + 9) * 128]) + __ldg(&Toc[(k13 * 16 + a4 + 11) * 128]);
            v.x = fmaxf(v.x, 0.f); v.y = fmaxf(v.y, 0.f);
            v.z = fmaxf(v.z, 0.f); v.w = fmaxf(v.w, 0.f);
            *(float4*)(op + jj) = v;
        }
    }
}

// deconv2: same FMA chains + cp.async double-buffered input staging.
__global__ __launch_bounds__(256) void deconv2_kernel(
    const float* __restrict__ w, float* __restrict__ recon) {
    __shared__ float wsp[CIN * DIM * 16];
    __shared__ float insb[2][1600];   // 8*10*20
    int n = blockIdx.z;
    int p0 = blockIdx.y * 16, q0 = blockIdx.x * 32;
    int tid = threadIdx.x, pl = tid >> 4, qi = tid & 15;
    int qp = qi & 1, jj = qi >> 1, a = pl & 1;
    int r0l = (pl + a) >> 1, c0l = qp + 2 * jj;
    int rb = p0 / 2 - 1, cb = q0 / 2 - 1;
    for (int i = tid; i < CIN * DIM * 16; i += 256) {
        int oc = i >> 11, rem = i & 2047;
        int ic = rem >> 4, k = rem & 15, kh = k >> 2, kw = k & 3;
        int slot = ic * 16 + ((kh & 1) * 2 + (kw & 1)) * 4 + ((kh >> 1) << 1) + (kw >> 1);
        wsp[oc * 2048 + slot] = w[i];
    }
    // prefetch stage 0
    for (int i = tid; i < 1440; i += 256) {
        int ic = i / 180, rem = i - ic * 180, r = rem / 18, c = rem - r * 18;
        int rr = rb + r, cc = cb + c;
        bool ok = ((unsigned)rr < H1) && ((unsigned)cc < H1);
        const float* src = ok ? &g_g[((n * DIM + ic) * H1 + rr) * H1 + cc] : g_g;
        cp4z(cvta_s(&insb[0][ic * 200 + r * 20 + c]), src, ok ? 4 : 0);
    }
    CP_COMMIT();

    u64 acc[3] = {0, 0, 0};
    for (int s = 0; s < 16; s++) {
        CP_WAIT0();
        __syncthreads();
        if (s < 15) {
            int ic0 = (s + 1) * 8;
            float* nb = insb[(s + 1) & 1];
            for (int i = tid; i < 1440; i += 256) {
                int ic = i / 180, rem = i - ic * 180, r = rem / 18, c = rem - r * 18;
                int rr = rb + r, cc = cb + c;
                bool ok = ((unsigned)rr < H1) && ((unsigned)cc < H1);
                const float* src = ok ? &g_g[((n * DIM + ic0 + ic) * H1 + rr) * H1 + cc] : g_g;
                cp4z(cvta_s(nb + ic * 200 + r * 20 + c), src, ok ? 4 : 0);
            }
            CP_COMMIT();
        }
        const float* buf = insb[s & 1];
        int ic0 = s * 8;
#pragma unroll
        for (int icl = 0; icl < 8; icl++) {
            const float* rp0 = buf + icl * 200 + r0l * 20;
            float t00 = rp0[c0l], t01 = rp0[c0l + 1], t02 = rp0[c0l + 2];
            float t10 = rp0[20 + c0l], t11 = rp0[20 + c0l + 1], t12 = rp0[20 + c0l + 2];
            u64 i0a = pack2(t00, t01), i0b = pack2(t01, t02);
            u64 i1a = pack2(t10, t11), i1b = pack2(t11, t12);
            int kb = (ic0 + icl) * 16 + (a * 2 + qp) * 4;
#pragma unroll
            for (int o = 0; o < 3; o++) {
                float4 wg = *(const float4*)&wsp[o * 2048 + kb];
                fma2(acc[o], i0a, pack2(wg.x, wg.x)); fma2(acc[o], i0b, pack2(wg.y, wg.y));
                fma2(acc[o], i1a, pack2(wg.z, wg.z)); fma2(acc[o], i1b, pack2(wg.w, wg.w));
            }
        }
    }
    int p = p0 + pl, q = q0 + qp + 4 * jj;
#pragma unroll
    for (int o = 0; o < 3; o++) {
        float2 v = unpack2(acc[o]);
        float* op = recon + ((n * CIN + o) * H0 + p) * H0;
        op[q] = tanhf(v.x);
        op[q + 2] = tanhf(v.y);
    }
}

#define VQ_SMEM ((128 * 68 + 128 * 132) * (int)sizeof(float))

extern "C" void kernel_launch(void* const* d_in, const int* in_sizes, int n_in,
                              void* d_out, int out_size) {
    const float* x    = (const float*)d_in[0];
    const float* w_e1 = (const float*)d_in[1];
    const float* w_e2 = (const float*)d_in[2];
    const float* emb  = (const float*)d_in[3];
    const float* w_d1 = (const float*)d_in[4];
    const float* w_d2 = (const float*)d_in[5];
    float* out = (float*)d_out;
    float* recon = out;
    float* ze = out + OFF_ZE;
    float* zq = out + OFF_ZQ;

    cudaFuncSetAttribute(vq_kernel, cudaFuncAttributeMaxDynamicSharedMemorySize, VQ_SMEM);
    cudaFuncSetAttribute(conv2_kernel, cudaFuncAttributeMaxDynamicSharedMemorySize, C2_SMEM);

    knorm_kernel<<<2, 256>>>(emb);
    tmat_kernel<<<128, 256>>>(emb, w_d1);
    conv1_kernel<<<dim3(H1, B), 256>>>(x, w_e1);
    conv2_kernel<<<dim3(8, 8, B), 256, C2_SMEM>>>(w_e2, ze);
    vq_kernel<<<1024, 256, VQ_SMEM>>>(ze, emb, zq);
    deconv1_gather_kernel<<<dim3(4, 16, B), 256>>>();
    deconv2_kernel<<<dim3(8, 16, B), 256>>>(w_d2, recon);
}

// round 12
// speedup vs baseline: 2.2376x; 1.0145x over previous
#include <cuda_runtime.h>
#include <math.h>

#define B 16
#define CIN 3
#define DIM 128
#define KCODES 512
#define H0 256
#define H1 128
#define H2 64
#define OFF_ZE  (B*CIN*H0*H0)
#define OFF_ZQ  (OFF_ZE + B*DIM*H2*H2)

__device__ float g_h[B*DIM*H1*H1];
__device__ float g_g[B*DIM*H1*H1];
__device__ float g_cnorm[KCODES];
__device__ int   g_idx[B*H2*H2];
__device__ float g_T[513*16*128];

typedef unsigned long long u64;
typedef unsigned int u32;
__device__ __forceinline__ void fma2(u64& d, u64 a, u64 b) {
    asm("fma.rn.f32x2 %0, %1, %2, %0;" : "+l"(d) : "l"(a), "l"(b));
}
__device__ __forceinline__ u64 pack2(float lo, float hi) {
    u64 r; asm("mov.b64 %0, {%1, %2};" : "=l"(r) : "f"(lo), "f"(hi)); return r;
}
__device__ __forceinline__ float2 unpack2(u64 v) {
    float2 r; asm("mov.b64 {%0, %1}, %2;" : "=f"(r.x), "=f"(r.y) : "l"(v)); return r;
}
__device__ __forceinline__ u64 lds2(const float* p) { return *(const u64*)p; }
__device__ __forceinline__ u32 cvta_s(const void* p) {
    u32 a; asm("{.reg .u64 t; cvta.to.shared.u64 t, %1; cvt.u32.u64 %0, t;}" : "=r"(a) : "l"(p));
    return a;
}
__device__ __forceinline__ void cp16(u32 d, const void* s) {
    asm volatile("cp.async.ca.shared.global [%0], [%1], 16;" :: "r"(d), "l"(s));
}
__device__ __forceinline__ void cp4z(u32 d, const void* s, int sz) {
    asm volatile("cp.async.ca.shared.global [%0], [%1], 4, %2;" :: "r"(d), "l"(s), "r"(sz));
}
#define CP_COMMIT() asm volatile("cp.async.commit_group;" ::: "memory")
#define CP_WAIT0()  asm volatile("cp.async.wait_group 0;" ::: "memory")

__global__ void knorm_kernel(const float* __restrict__ emb) {
    int k = blockIdx.x * blockDim.x + threadIdx.x;
    if (k < KCODES) {
        const float* e = emb + k * DIM;
        float s = 0.f;
#pragma unroll 8
        for (int d = 0; d < DIM; d++) s += e[d] * e[d];
        g_cnorm[k] = s;
    }
}

__global__ __launch_bounds__(256) void tmat_kernel(
    const float* __restrict__ emb, const float* __restrict__ wd1) {
    __shared__ float ws[2048];
    int oc = blockIdx.x, tid = threadIdx.x;
    for (int i = tid; i < 2048; i += 256) ws[i] = wd1[oc * 2048 + i];
    __syncthreads();
    for (int k = tid; k < 513; k += 256) {
        float acc[16];
#pragma unroll
        for (int t = 0; t < 16; t++) acc[t] = 0.f;
        if (k < 512) {
            const float* e = emb + k * DIM;
            for (int ic = 0; ic < 128; ic++) {
                float ev = __ldg(e + ic);
                const float* wp = &ws[ic * 16];
#pragma unroll
                for (int t = 0; t < 16; t++) acc[t] += ev * wp[t];
            }
        }
#pragma unroll
        for (int t = 0; t < 16; t++) g_T[(k * 16 + t) * 128 + oc] = acc[t];
    }
}

// conv1 (unchanged)
__global__ __launch_bounds__(256) void conv1_kernel(
    const float* __restrict__ x, const float* __restrict__ w) {
    __shared__ float ws[DIM * 48];
    __shared__ float ins[CIN][4][260];
    int n = blockIdx.y, oy = blockIdx.x, tid = threadIdx.x;
    for (int i = tid; i < DIM * 48; i += 256) ws[i] = w[i];
    int iyb = oy * 2 - 1;
    for (int i = tid; i < CIN * 4 * 258; i += 256) {
        int ic = i / 1032, rem = i - ic * 1032, r = rem / 258, c = rem - r * 258;
        int iy = iyb + r, ix = c - 1;
        float v = 0.f;
        if ((unsigned)iy < H0 && (unsigned)ix < H0) v = x[((n * CIN + ic) * H0 + iy) * H0 + ix];
        ins[ic][r][c] = v;
    }
    __syncthreads();
    int oc = tid >> 1, half = tid & 1;
    u64 wp[24];
#pragma unroll
    for (int ic = 0; ic < 3; ic++)
#pragma unroll
        for (int kh = 0; kh < 4; kh++) {
            const float* wk = &ws[oc * 48 + ic * 16 + kh * 4];
            wp[(ic * 4 + kh) * 2] = pack2(wk[0], wk[1]);
            wp[(ic * 4 + kh) * 2 + 1] = pack2(wk[2], wk[3]);
        }
    float* outp = g_h + ((n * DIM + oc) * H1 + oy) * H1;
    for (int k = 0; k < 64; k += 4) {
        int oxa = half + 2 * k;
        u64 a0 = 0, a1 = 0, a2 = 0, a3 = 0;
#pragma unroll
        for (int ic = 0; ic < 3; ic++)
#pragma unroll
            for (int kh = 0; kh < 4; kh++) {
                const float* rp = &ins[ic][kh][2 * oxa];
                u64 w01 = wp[(ic * 4 + kh) * 2], w23 = wp[(ic * 4 + kh) * 2 + 1];
                fma2(a0, lds2(rp),      w01); fma2(a0, lds2(rp + 2),  w23);
                fma2(a1, lds2(rp + 4),  w01); fma2(a1, lds2(rp + 6),  w23);
                fma2(a2, lds2(rp + 8),  w01); fma2(a2, lds2(rp + 10), w23);
                fma2(a3, lds2(rp + 12), w01); fma2(a3, lds2(rp + 14), w23);
            }
        float2 v0 = unpack2(a0), v1 = unpack2(a1), v2 = unpack2(a2), v3 = unpack2(a3);
        outp[oxa]     = fmaxf(v0.x + v0.y, 0.f);
        outp[oxa + 2] = fmaxf(v1.x + v1.y, 0.f);
        outp[oxa + 4] = fmaxf(v2.x + v2.y, 0.f);
        outp[oxa + 6] = fmaxf(v3.x + v3.y, 0.f);
    }
}

// conv2: identical FMA chains; staging addresses hoisted into smem table.
#define C2_TBL_F 3072
#define C2_WS_F  8704
#define C2_BUF_F (C2_WS_F + 1584)
#define C2_SMEM  ((C2_TBL_F + 2 * C2_BUF_F) * 4)

__global__ __launch_bounds__(256, 2) void conv2_kernel(
    const float* __restrict__ w, float* __restrict__ ze) {
    extern __shared__ float s2[];
    uint2* tbl = (uint2*)s2;
    float* bufs = s2 + C2_TBL_F;
    int tid = threadIdx.x;
    int n = blockIdx.z, oy0 = blockIdx.y * 8, ox0 = blockIdx.x * 8;
    int ocg = tid >> 3, oyl = tid & 7;
    int iyb = oy0 * 2 - 1, ixb = ox0 * 2 - 1;
    u32 sbase = cvta_s(bufs);

    // build per-thread staging table (6 entries)
    uint2* myt = tbl + tid * 6;
#pragma unroll
    for (int j = 0; j < 6; j++) {
        int i = tid + j * 256;
        u32 gof = 0, sof = (u32)((C2_WS_F + 19) * 4);
        if (i < 1296) {
            int ic = i / 324, rem = i - ic * 324, r = rem / 18, c = rem - r * 18;
            int iy = iyb + r, ix = ixb + c;
            bool ok = ((unsigned)iy < H1) && ((unsigned)ix < H1);
            sof = (u32)((C2_WS_F + ic * 396 + r * 22 + c) * 4) | (ok ? 1u : 0u);
            if (ok) gof = (u32)(((n * DIM + ic) * H1 + iy) * H1 + ix);
        }
        myt[j] = make_uint2(gof, sof);
    }
    int woc0 = tid >> 4;
    u32 wdofs = (u32)(woc0 * 68 * 4 + (tid & 15) * 16);
    const float* wsrc = w + woc0 * 2048 + (tid & 15) * 4;

    u64 acc[4][8];
#pragma unroll
    for (int o = 0; o < 4; o++)
#pragma unroll
        for (int j = 0; j < 8; j++) acc[o][j] = 0;

    // prefetch stage 0
    {
        u32 bb = sbase;
#pragma unroll
        for (int jj = 0; jj < 8; jj++)
            cp16(bb + wdofs + jj * (16 * 68 * 4), wsrc + jj * (16 * 2048));
#pragma unroll
        for (int jj = 0; jj < 5; jj++) {
            uint2 e = myt[jj];
            cp4z(bb + (e.y & ~1u), g_h + e.x, (e.y & 1) * 4);
        }
        if (tid < 16) {
            uint2 e = myt[5];
            cp4z(bb + (e.y & ~1u), g_h + e.x, (e.y & 1) * 4);
        }
    }
    CP_COMMIT();

    for (int st = 0; st < 32; st++) {
        CP_WAIT0();
        __syncthreads();
        if (st < 31) {
            u32 bb = sbase + ((st + 1) & 1) * (C2_BUF_F * 4);
            const float* wsp = wsrc + (st + 1) * 64;
            const float* gbase = g_h + (st + 1) * 65536;
#pragma unroll
            for (int jj = 0; jj < 8; jj++)
                cp16(bb + wdofs + jj * (16 * 68 * 4), wsp + jj * (16 * 2048));
#pragma unroll
            for (int jj = 0; jj < 5; jj++) {
                uint2 e = myt[jj];
                cp4z(bb + (e.y & ~1u), gbase + e.x, (e.y & 1) * 4);
            }
            if (tid < 16) {
                uint2 e = myt[5];
                cp4z(bb + (e.y & ~1u), gbase + e.x, (e.y & 1) * 4);
            }
            CP_COMMIT();
        }
        float* wsb = bufs + (st & 1) * C2_BUF_F;
        float* insb = wsb + C2_WS_F;
#pragma unroll
        for (int icl = 0; icl < 4; icl++) {
#pragma unroll
            for (int kh = 0; kh < 4; kh++) {
                const float* rp = insb + icl * 396 + (oyl * 2 + kh) * 22;
                u64 ivp[9];
#pragma unroll
                for (int m = 0; m < 9; m++) ivp[m] = lds2(rp + 2 * m);
#pragma unroll
                for (int o = 0; o < 4; o++) {
                    const float* wpt = wsb + (ocg * 4 + o) * 68 + icl * 16 + kh * 4;
                    u64 w01 = lds2(wpt), w23 = lds2(wpt + 2);
#pragma unroll
                    for (int j = 0; j < 8; j++) {
                        fma2(acc[o][j], ivp[j], w01);
                        fma2(acc[o][j], ivp[j + 1], w23);
                    }
                }
            }
        }
    }
    int oy = oy0 + oyl;
#pragma unroll
    for (int o = 0; o < 4; o++) {
        float* op = ze + ((n * DIM + ocg * 4 + o) * H2 + oy) * H2 + ox0;
#pragma unroll
        for (int j = 0; j < 8; j++) {
            float2 v = unpack2(acc[o][j]);
            op[j] = v.x + v.y;
        }
    }
}

// VQ (unchanged from R11)
__global__ __launch_bounds__(256) void vq_kernel(
    const float* __restrict__ ze, const float* __restrict__ emb, float* __restrict__ zq) {
    extern __shared__ float sm[];
    float* z_s = sm;
    float* c_s = sm + 128 * 68;
    __shared__ int idx_s[64];
    int tid = threadIdx.x;
    int v0 = blockIdx.x * 64, b = v0 >> 12, s0 = v0 & 4095;
    for (int i = tid; i < 2048; i += 256) {
        int d = i >> 4, vl4 = (i & 15) * 4;
        *(float4*)&z_s[d * 68 + vl4] = *(const float4*)&ze[(b * DIM + d) * 4096 + s0 + vl4];
    }
    int vg = tid >> 4, cg = tid & 15;
    float minv[4]; int mini[4];
#pragma unroll
    for (int v = 0; v < 4; v++) { minv[v] = 3.0e38f; mini[v] = 0; }
    u64 dot[2][8];
#pragma unroll
    for (int vp = 0; vp < 2; vp++)
#pragma unroll
        for (int c = 0; c < 8; c++) dot[vp][c] = 0;
    for (int ch = 0; ch < 4; ch++) {
        __syncthreads();
        int cbase = ch * 128;
        for (int i = tid; i < 4096; i += 256) {
            int cl = i & 127, dq = (i >> 7) * 4;
            float4 t = *(const float4*)&emb[(cbase + cl) * DIM + dq];
            c_s[dq * 132 + cl] = t.x; c_s[(dq + 1) * 132 + cl] = t.y;
            c_s[(dq + 2) * 132 + cl] = t.z; c_s[(dq + 3) * 132 + cl] = t.w;
        }
        __syncthreads();
#pragma unroll 2
        for (int d = 0; d < 128; d++) {
            const float* zp = &z_s[d * 68 + vg * 4];
            float4 z0 = *(const float4*)zp;
            u64 zpk[2] = {pack2(z0.x, z0.y), pack2(z0.z, z0.w)};
            const float* cp = &c_s[d * 132];
            float4 c0 = *(const float4*)(cp + cg * 4), c1 = *(const float4*)(cp + 64 + cg * 4);
            u64 cb[8] = {pack2(c0.x, c0.x), pack2(c0.y, c0.y), pack2(c0.z, c0.z), pack2(c0.w, c0.w),
                         pack2(c1.x, c1.x), pack2(c1.y, c1.y), pack2(c1.z, c1.z), pack2(c1.w, c1.w)};
#pragma unroll
            for (int vp = 0; vp < 2; vp++)
#pragma unroll
                for (int c = 0; c < 8; c++) fma2(dot[vp][c], zpk[vp], cb[c]);
        }
#pragma unroll
        for (int c = 0; c < 8; c++) {
            int code = cbase + (c < 4 ? cg * 4 + c : 64 + cg * 4 + (c - 4));
            float cn = g_cnorm[code];
#pragma unroll
            for (int vp = 0; vp < 2; vp++) {
                float2 dv = unpack2(dot[vp][c]);
                float d0 = fmaf(-2.f, dv.x, cn), d1 = fmaf(-2.f, dv.y, cn);
                if (d0 < minv[2 * vp]) { minv[2 * vp] = d0; mini[2 * vp] = code; }
                if (d1 < minv[2 * vp + 1]) { minv[2 * vp + 1] = d1; mini[2 * vp + 1] = code; }
                dot[vp][c] = 0;
            }
        }
    }
    __syncthreads();
    float* rd = c_s; int* ri = (int*)(c_s + 1024);
#pragma unroll
    for (int v = 0; v < 4; v++) {
        int vl = vg * 4 + v;
        rd[vl * 16 + cg] = minv[v]; ri[vl * 16 + cg] = mini[v];
    }
    __syncthreads();
    if (tid < 64) {
        float bd = rd[tid * 16]; int bi = ri[tid * 16];
        for (int g = 1; g < 16; g++) {
            float d2 = rd[tid * 16 + g]; int i2 = ri[tid * 16 + g];
            if (d2 < bd || (d2 == bd && i2 < bi)) { bd = d2; bi = i2; }
        }
        idx_s[tid] = bi;
        g_idx[v0 + tid] = bi;
    }
    __syncthreads();
    for (int i = tid; i < 8192; i += 256) {
        int d = i >> 6, vl = i & 63;
        zq[(b * DIM + d) * 4096 + s0 + vl] = __ldg(&emb[idx_s[vl] * DIM + d]);
    }
}

// deconv1 gather (unchanged)
__global__ __launch_bounds__(256) void deconv1_gather_kernel() {
    __shared__ int sidx[6][18];
    int n = blockIdx.z, p0 = blockIdx.y * 8, q0 = blockIdx.x * 32;
    int tid = threadIdx.x;
    int rb = p0 / 2 - 1, cb = q0 / 2 - 1;
    for (int i = tid; i < 108; i += 256) {
        int r = i / 18, c = i - r * 18;
        int rr = rb + r, cc = cb + c;
        sidx[r][c] = ((unsigned)rr < H2 && (unsigned)cc < H2)
                     ? g_idx[n * 4096 + rr * 64 + cc] : 512;
    }
    __syncthreads();
    int oc = tid & 127, half = tid >> 7;
    const float* Toc = g_T + oc;
#pragma unroll
    for (int s = 0; s < 4; s++) {
        int pl = half * 4 + s, p = p0 + pl;
        int a4 = (p & 1) * 4;
        int rl = (pl + (p & 1)) >> 1;
        const int* r0 = sidx[rl];
        const int* r1 = sidx[rl + 1];
        float* op = g_g + ((n * DIM + oc) * H1 + p) * H1 + q0;
        for (int jj = 0; jj < 32; jj += 4) {
            int cl = jj >> 1;
            int k00 = r0[cl], k01 = r0[cl + 1], k02 = r0[cl + 2], k03 = r0[cl + 3];
            int k10 = r1[cl], k11 = r1[cl + 1], k12 = r1[cl + 2], k13 = r1[cl + 3];
            float4 v;
            v.x = __ldg(&Toc[(k00 * 16 + a4)     * 128]) + __ldg(&Toc[(k01 * 16 + a4 + 2)  * 128])
                + __ldg(&Toc[(k10 * 16 + a4 + 8) * 128]) + __ldg(&Toc[(k11 * 16 + a4 + 10) * 128]);
            v.y = __ldg(&Toc[(k01 * 16 + a4 + 1) * 128]) + __ldg(&Toc[(k02 * 16 + a4 + 3)  * 128])
                + __ldg(&Toc[(k11 * 16 + a4 + 9) * 128]) + __ldg(&Toc[(k12 * 16 + a4 + 11) * 128]);
            v.z = __ldg(&Toc[(k01 * 16 + a4)     * 128]) + __ldg(&Toc[(k02 * 16 + a4 + 2)  * 128])
                + __ldg(&Toc[(k11 * 16 + a4 + 8) * 128]) + __ldg(&Toc[(k12 * 16 + a4 + 10) * 128]);
            v.w = __ldg(&Toc[(k02 * 16 + a4 + 1) * 128]) + __ldg(&Toc[(k03 * 16 + a4 + 3)  * 128])
                + __ldg(&Toc[(k12 * 16 + a4 + 9) * 128]) + __ldg(&Toc[(k13 * 16 + a4 + 11) * 128]);
            v.x = fmaxf(v.x, 0.f); v.y = fmaxf(v.y, 0.f);
            v.z = fmaxf(v.z, 0.f); v.w = fmaxf(v.w, 0.f);
            *(float4*)(op + jj) = v;
        }
    }
}

// deconv2: duplicated u64 weights in dynamic smem (kills broadcast MOVs).
#define D2_W_U64 (CIN * 2048)
#define D2_SMEM  (D2_W_U64 * 8 + 2 * 1600 * 4)

__global__ __launch_bounds__(256) void deconv2_kernel(
    const float* __restrict__ w, float* __restrict__ recon) {
    extern __shared__ u64 sd2[];
    u64* wsp2 = sd2;
    float* insb = (float*)(sd2 + D2_W_U64);
    int n = blockIdx.z;
    int p0 = blockIdx.y * 16, q0 = blockIdx.x * 32;
    int tid = threadIdx.x, pl = tid >> 4, qi = tid & 15;
    int qp = qi & 1, jj = qi >> 1, a = pl & 1;
    int r0l = (pl + a) >> 1, c0l = qp + 2 * jj;
    int rb = p0 / 2 - 1, cb = q0 / 2 - 1;
    for (int i = tid; i < CIN * DIM * 16; i += 256) {
        int oc = i >> 11, rem = i & 2047;
        int ic = rem >> 4, k = rem & 15, kh = k >> 2, kw = k & 3;
        int slot = ic * 16 + ((kh & 1) * 2 + (kw & 1)) * 4 + ((kh >> 1) << 1) + (kw >> 1);
        float v = w[i];
        wsp2[oc * 2048 + slot] = pack2(v, v);
    }
    for (int i = tid; i < 1440; i += 256) {
        int ic = i / 180, rem = i - ic * 180, r = rem / 18, c = rem - r * 18;
        int rr = rb + r, cc = cb + c;
        bool ok = ((unsigned)rr < H1) && ((unsigned)cc < H1);
        const float* src = ok ? &g_g[((n * DIM + ic) * H1 + rr) * H1 + cc] : g_g;
        cp4z(cvta_s(insb + ic * 200 + r * 20 + c), src, ok ? 4 : 0);
    }
    CP_COMMIT();

    u64 acc[3] = {0, 0, 0};
    for (int s = 0; s < 16; s++) {
        CP_WAIT0();
        __syncthreads();
        if (s < 15) {
            int ic0 = (s + 1) * 8;
            float* nb = insb + ((s + 1) & 1) * 1600;
            for (int i = tid; i < 1440; i += 256) {
                int ic = i / 180, rem = i - ic * 180, r = rem / 18, c = rem - r * 18;
                int rr = rb + r, cc = cb + c;
                bool ok = ((unsigned)rr < H1) && ((unsigned)cc < H1);
                const float* src = ok ? &g_g[((n * DIM + ic0 + ic) * H1 + rr) * H1 + cc] : g_g;
                cp4z(cvta_s(nb + ic * 200 + r * 20 + c), src, ok ? 4 : 0);
            }
            CP_COMMIT();
        }
        const float* buf = insb + (s & 1) * 1600;
        int ic0 = s * 8;
#pragma unroll
        for (int icl = 0; icl < 8; icl++) {
            const float* rp0 = buf + icl * 200 + r0l * 20;
            float t00 = rp0[c0l], t01 = rp0[c0l + 1], t02 = rp0[c0l + 2];
            float t10 = rp0[20 + c0l], t11 = rp0[20 + c0l + 1], t12 = rp0[20 + c0l + 2];
            u64 i0a = pack2(t00, t01), i0b = pack2(t01, t02);
            u64 i1a = pack2(t10, t11), i1b = pack2(t11, t12);
            int kb = (ic0 + icl) * 16 + (a * 2 + qp) * 4;
#pragma unroll
            for (int o = 0; o < 3; o++) {
                const u64* wp = wsp2 + o * 2048 + kb;
                fma2(acc[o], i0a, wp[0]); fma2(acc[o], i0b, wp[1]);
                fma2(acc[o], i1a, wp[2]); fma2(acc[o], i1b, wp[3]);
            }
        }
    }
    int p = p0 + pl, q = q0 + qp + 4 * jj;
#pragma unroll
    for (int o = 0; o < 3; o++) {
        float2 v = unpack2(acc[o]);
        float* op = recon + ((n * CIN + o) * H0 + p) * H0;
        op[q] = tanhf(v.x);
        op[q + 2] = tanhf(v.y);
    }
}

#define VQ_SMEM ((128 * 68 + 128 * 132) * (int)sizeof(float))

extern "C" void kernel_launch(void* const* d_in, const int* in_sizes, int n_in,
                              void* d_out, int out_size) {
    const float* x    = (const float*)d_in[0];
    const float* w_e1 = (const float*)d_in[1];
    const float* w_e2 = (const float*)d_in[2];
    const float* emb  = (const float*)d_in[3];
    const float* w_d1 = (const float*)d_in[4];
    const float* w_d2 = (const float*)d_in[5];
    float* out = (float*)d_out;
    float* recon = out;
    float* ze = out + OFF_ZE;
    float* zq = out + OFF_ZQ;

    cudaFuncSetAttribute(vq_kernel, cudaFuncAttributeMaxDynamicSharedMemorySize, VQ_SMEM);
    cudaFuncSetAttribute(conv2_kernel, cudaFuncAttributeMaxDynamicSharedMemorySize, C2_SMEM);
    cudaFuncSetAttribute(deconv2_kernel, cudaFuncAttributeMaxDynamicSharedMemorySize, D2_SMEM);

    knorm_kernel<<<2, 256>>>(emb);
    tmat_kernel<<<128, 256>>>(emb, w_d1);
    conv1_kernel<<<dim3(H1, B), 256>>>(x, w_e1);
    conv2_kernel<<<dim3(8, 8, B), 256, C2_SMEM>>>(w_e2, ze);
    vq_kernel<<<1024, 256, VQ_SMEM>>>(ze, emb, zq);
    deconv1_gather_kernel<<<dim3(4, 16, B), 256>>>();
    deconv2_kernel<<<dim3(8, 16, B), 256, D2_SMEM>>>(w_d2, recon);
}

// round 13
// speedup vs baseline: 2.2901x; 1.0234x over previous
#include <cuda_runtime.h>
#include <math.h>

#define B 16
#define CIN 3
#define DIM 128
#define KCODES 512
#define H0 256
#define H1 128
#define H2 64
#define OFF_ZE  (B*CIN*H0*H0)
#define OFF_ZQ  (OFF_ZE + B*DIM*H2*H2)

__device__ float g_h[B*DIM*H1*H1];
__device__ float g_g[B*DIM*H1*H1];
__device__ float g_cnorm[KCODES];
__device__ int   g_idx[B*H2*H2];
__device__ float g_T[513*16*128];

typedef unsigned long long u64;
typedef unsigned int u32;
__device__ __forceinline__ void fma2(u64& d, u64 a, u64 b) {
    asm("fma.rn.f32x2 %0, %1, %2, %0;" : "+l"(d) : "l"(a), "l"(b));
}
__device__ __forceinline__ u64 pack2(float lo, float hi) {
    u64 r; asm("mov.b64 %0, {%1, %2};" : "=l"(r) : "f"(lo), "f"(hi)); return r;
}
__device__ __forceinline__ float2 unpack2(u64 v) {
    float2 r; asm("mov.b64 {%0, %1}, %2;" : "=f"(r.x), "=f"(r.y) : "l"(v)); return r;
}
__device__ __forceinline__ u64 lds2(const float* p) { return *(const u64*)p; }
__device__ __forceinline__ u32 cvta_s(const void* p) {
    u32 a; asm("{.reg .u64 t; cvta.to.shared.u64 t, %1; cvt.u32.u64 %0, t;}" : "=r"(a) : "l"(p));
    return a;
}
__device__ __forceinline__ void cp16(u32 d, const void* s) {
    asm volatile("cp.async.ca.shared.global [%0], [%1], 16;" :: "r"(d), "l"(s));
}
__device__ __forceinline__ void cp4z(u32 d, const void* s, int sz) {
    asm volatile("cp.async.ca.shared.global [%0], [%1], 4, %2;" :: "r"(d), "l"(s), "r"(sz));
}
#define CP_COMMIT() asm volatile("cp.async.commit_group;" ::: "memory")
#define CP_WAIT0()  asm volatile("cp.async.wait_group 0;" ::: "memory")

__global__ void knorm_kernel(const float* __restrict__ emb) {
    int k = blockIdx.x * blockDim.x + threadIdx.x;
    if (k < KCODES) {
        const float* e = emb + k * DIM;
        float s = 0.f;
#pragma unroll 8
        for (int d = 0; d < DIM; d++) s += e[d] * e[d];
        g_cnorm[k] = s;
    }
}

__global__ __launch_bounds__(256) void tmat_kernel(
    const float* __restrict__ emb, const float* __restrict__ wd1) {
    __shared__ float ws[2048];
    int oc = blockIdx.x, tid = threadIdx.x;
    for (int i = tid; i < 2048; i += 256) ws[i] = wd1[oc * 2048 + i];
    __syncthreads();
    for (int k = tid; k < 513; k += 256) {
        float acc[16];
#pragma unroll
        for (int t = 0; t < 16; t++) acc[t] = 0.f;
        if (k < 512) {
            const float* e = emb + k * DIM;
            for (int ic = 0; ic < 128; ic++) {
                float ev = __ldg(e + ic);
                const float* wp = &ws[ic * 16];
#pragma unroll
                for (int t = 0; t < 16; t++) acc[t] += ev * wp[t];
            }
        }
#pragma unroll
        for (int t = 0; t < 16; t++) g_T[(k * 16 + t) * 128 + oc] = acc[t];
    }
}

// conv1 (unchanged)
__global__ __launch_bounds__(256) void conv1_kernel(
    const float* __restrict__ x, const float* __restrict__ w) {
    __shared__ float ws[DIM * 48];
    __shared__ float ins[CIN][4][260];
    int n = blockIdx.y, oy = blockIdx.x, tid = threadIdx.x;
    for (int i = tid; i < DIM * 48; i += 256) ws[i] = w[i];
    int iyb = oy * 2 - 1;
    for (int i = tid; i < CIN * 4 * 258; i += 256) {
        int ic = i / 1032, rem = i - ic * 1032, r = rem / 258, c = rem - r * 258;
        int iy = iyb + r, ix = c - 1;
        float v = 0.f;
        if ((unsigned)iy < H0 && (unsigned)ix < H0) v = x[((n * CIN + ic) * H0 + iy) * H0 + ix];
        ins[ic][r][c] = v;
    }
    __syncthreads();
    int oc = tid >> 1, half = tid & 1;
    u64 wp[24];
#pragma unroll
    for (int ic = 0; ic < 3; ic++)
#pragma unroll
        for (int kh = 0; kh < 4; kh++) {
            const float* wk = &ws[oc * 48 + ic * 16 + kh * 4];
            wp[(ic * 4 + kh) * 2] = pack2(wk[0], wk[1]);
            wp[(ic * 4 + kh) * 2 + 1] = pack2(wk[2], wk[3]);
        }
    float* outp = g_h + ((n * DIM + oc) * H1 + oy) * H1;
    for (int k = 0; k < 64; k += 4) {
        int oxa = half + 2 * k;
        u64 a0 = 0, a1 = 0, a2 = 0, a3 = 0;
#pragma unroll
        for (int ic = 0; ic < 3; ic++)
#pragma unroll
            for (int kh = 0; kh < 4; kh++) {
                const float* rp = &ins[ic][kh][2 * oxa];
                u64 w01 = wp[(ic * 4 + kh) * 2], w23 = wp[(ic * 4 + kh) * 2 + 1];
                fma2(a0, lds2(rp),      w01); fma2(a0, lds2(rp + 2),  w23);
                fma2(a1, lds2(rp + 4),  w01); fma2(a1, lds2(rp + 6),  w23);
                fma2(a2, lds2(rp + 8),  w01); fma2(a2, lds2(rp + 10), w23);
                fma2(a3, lds2(rp + 12), w01); fma2(a3, lds2(rp + 14), w23);
            }
        float2 v0 = unpack2(a0), v1 = unpack2(a1), v2 = unpack2(a2), v3 = unpack2(a3);
        outp[oxa]     = fmaxf(v0.x + v0.y, 0.f);
        outp[oxa + 2] = fmaxf(v1.x + v1.y, 0.f);
        outp[oxa + 4] = fmaxf(v2.x + v2.y, 0.f);
        outp[oxa + 6] = fmaxf(v3.x + v3.y, 0.f);
    }
}

// conv2: FMA chains bitwise-identical; weight pair now one LDS.128.
#define C2_TBL_F 3072
#define C2_WS_F  8704
#define C2_BUF_F (C2_WS_F + 1584)
#define C2_SMEM  ((C2_TBL_F + 2 * C2_BUF_F) * 4)

__global__ __launch_bounds__(256, 2) void conv2_kernel(
    const float* __restrict__ w, float* __restrict__ ze) {
    extern __shared__ float s2[];
    uint2* tbl = (uint2*)s2;
    float* bufs = s2 + C2_TBL_F;
    int tid = threadIdx.x;
    int n = blockIdx.z, oy0 = blockIdx.y * 8, ox0 = blockIdx.x * 8;
    int ocg = tid >> 3, oyl = tid & 7;
    int iyb = oy0 * 2 - 1, ixb = ox0 * 2 - 1;
    u32 sbase = cvta_s(bufs);

    uint2* myt = tbl + tid * 6;
#pragma unroll
    for (int j = 0; j < 6; j++) {
        int i = tid + j * 256;
        u32 gof = 0, sof = (u32)((C2_WS_F + 19) * 4);
        if (i < 1296) {
            int ic = i / 324, rem = i - ic * 324, r = rem / 18, c = rem - r * 18;
            int iy = iyb + r, ix = ixb + c;
            bool ok = ((unsigned)iy < H1) && ((unsigned)ix < H1);
            sof = (u32)((C2_WS_F + ic * 396 + r * 22 + c) * 4) | (ok ? 1u : 0u);
            if (ok) gof = (u32)(((n * DIM + ic) * H1 + iy) * H1 + ix);
        }
        myt[j] = make_uint2(gof, sof);
    }
    int woc0 = tid >> 4;
    u32 wdofs = (u32)(woc0 * 68 * 4 + (tid & 15) * 16);
    const float* wsrc = w + woc0 * 2048 + (tid & 15) * 4;

    u64 acc[4][8];
#pragma unroll
    for (int o = 0; o < 4; o++)
#pragma unroll
        for (int j = 0; j < 8; j++) acc[o][j] = 0;

    {
        u32 bb = sbase;
#pragma unroll
        for (int jj = 0; jj < 8; jj++)
            cp16(bb + wdofs + jj * (16 * 68 * 4), wsrc + jj * (16 * 2048));
#pragma unroll
        for (int jj = 0; jj < 5; jj++) {
            uint2 e = myt[jj];
            cp4z(bb + (e.y & ~1u), g_h + e.x, (e.y & 1) * 4);
        }
        if (tid < 16) {
            uint2 e = myt[5];
            cp4z(bb + (e.y & ~1u), g_h + e.x, (e.y & 1) * 4);
        }
    }
    CP_COMMIT();

    for (int st = 0; st < 32; st++) {
        CP_WAIT0();
        __syncthreads();
        if (st < 31) {
            u32 bb = sbase + ((st + 1) & 1) * (C2_BUF_F * 4);
            const float* wsp = wsrc + (st + 1) * 64;
            const float* gbase = g_h + (st + 1) * 65536;
#pragma unroll
            for (int jj = 0; jj < 8; jj++)
                cp16(bb + wdofs + jj * (16 * 68 * 4), wsp + jj * (16 * 2048));
#pragma unroll
            for (int jj = 0; jj < 5; jj++) {
                uint2 e = myt[jj];
                cp4z(bb + (e.y & ~1u), gbase + e.x, (e.y & 1) * 4);
            }
            if (tid < 16) {
                uint2 e = myt[5];
                cp4z(bb + (e.y & ~1u), gbase + e.x, (e.y & 1) * 4);
            }
            CP_COMMIT();
        }
        float* wsb = bufs + (st & 1) * C2_BUF_F;
        float* insb = wsb + C2_WS_F;
#pragma unroll
        for (int icl = 0; icl < 4; icl++) {
#pragma unroll
            for (int kh = 0; kh < 4; kh++) {
                const float* rp = insb + icl * 396 + (oyl * 2 + kh) * 22;
                u64 ivp[9];
#pragma unroll
                for (int m = 0; m < 9; m++) ivp[m] = lds2(rp + 2 * m);
#pragma unroll
                for (int o = 0; o < 4; o++) {
                    const ulonglong2* wpt = (const ulonglong2*)
                        (wsb + (ocg * 4 + o) * 68 + icl * 16 + kh * 4);
                    ulonglong2 wv = *wpt;
#pragma unroll
                    for (int j = 0; j < 8; j++) {
                        fma2(acc[o][j], ivp[j], wv.x);
                        fma2(acc[o][j], ivp[j + 1], wv.y);
                    }
                }
            }
        }
    }
    int oy = oy0 + oyl;
#pragma unroll
    for (int o = 0; o < 4; o++) {
        float* op = ze + ((n * DIM + ocg * 4 + o) * H2 + oy) * H2 + ox0;
#pragma unroll
        for (int j = 0; j < 8; j++) {
            float2 v = unpack2(acc[o][j]);
            op[j] = v.x + v.y;
        }
    }
}

// VQ (unchanged)
__global__ __launch_bounds__(256) void vq_kernel(
    const float* __restrict__ ze, const float* __restrict__ emb, float* __restrict__ zq) {
    extern __shared__ float sm[];
    float* z_s = sm;
    float* c_s = sm + 128 * 68;
    __shared__ int idx_s[64];
    int tid = threadIdx.x;
    int v0 = blockIdx.x * 64, b = v0 >> 12, s0 = v0 & 4095;
    for (int i = tid; i < 2048; i += 256) {
        int d = i >> 4, vl4 = (i & 15) * 4;
        *(float4*)&z_s[d * 68 + vl4] = *(const float4*)&ze[(b * DIM + d) * 4096 + s0 + vl4];
    }
    int vg = tid >> 4, cg = tid & 15;
    float minv[4]; int mini[4];
#pragma unroll
    for (int v = 0; v < 4; v++) { minv[v] = 3.0e38f; mini[v] = 0; }
    u64 dot[2][8];
#pragma unroll
    for (int vp = 0; vp < 2; vp++)
#pragma unroll
        for (int c = 0; c < 8; c++) dot[vp][c] = 0;
    for (int ch = 0; ch < 4; ch++) {
        __syncthreads();
        int cbase = ch * 128;
        for (int i = tid; i < 4096; i += 256) {
            int cl = i & 127, dq = (i >> 7) * 4;
            float4 t = *(const float4*)&emb[(cbase + cl) * DIM + dq];
            c_s[dq * 132 + cl] = t.x; c_s[(dq + 1) * 132 + cl] = t.y;
            c_s[(dq + 2) * 132 + cl] = t.z; c_s[(dq + 3) * 132 + cl] = t.w;
        }
        __syncthreads();
#pragma unroll 2
        for (int d = 0; d < 128; d++) {
            const float* zp = &z_s[d * 68 + vg * 4];
            float4 z0 = *(const float4*)zp;
            u64 zpk[2] = {pack2(z0.x, z0.y), pack2(z0.z, z0.w)};
            const float* cp = &c_s[d * 132];
            float4 c0 = *(const float4*)(cp + cg * 4), c1 = *(const float4*)(cp + 64 + cg * 4);
            u64 cb[8] = {pack2(c0.x, c0.x), pack2(c0.y, c0.y), pack2(c0.z, c0.z), pack2(c0.w, c0.w),
                         pack2(c1.x, c1.x), pack2(c1.y, c1.y), pack2(c1.z, c1.z), pack2(c1.w, c1.w)};
#pragma unroll
            for (int vp = 0; vp < 2; vp++)
#pragma unroll
                for (int c = 0; c < 8; c++) fma2(dot[vp][c], zpk[vp], cb[c]);
        }
#pragma unroll
        for (int c = 0; c < 8; c++) {
            int code = cbase + (c < 4 ? cg * 4 + c : 64 + cg * 4 + (c - 4));
            float cn = g_cnorm[code];
#pragma unroll
            for (int vp = 0; vp < 2; vp++) {
                float2 dv = unpack2(dot[vp][c]);
                float d0 = fmaf(-2.f, dv.x, cn), d1 = fmaf(-2.f, dv.y, cn);
                if (d0 < minv[2 * vp]) { minv[2 * vp] = d0; mini[2 * vp] = code; }
                if (d1 < minv[2 * vp + 1]) { minv[2 * vp + 1] = d1; mini[2 * vp + 1] = code; }
                dot[vp][c] = 0;
            }
        }
    }
    __syncthreads();
    float* rd = c_s; int* ri = (int*)(c_s + 1024);
#pragma unroll
    for (int v = 0; v < 4; v++) {
        int vl = vg * 4 + v;
        rd[vl * 16 + cg] = minv[v]; ri[vl * 16 + cg] = mini[v];
    }
    __syncthreads();
    if (tid < 64) {
        float bd = rd[tid * 16]; int bi = ri[tid * 16];
        for (int g = 1; g < 16; g++) {
            float d2 = rd[tid * 16 + g]; int i2 = ri[tid * 16 + g];
            if (d2 < bd || (d2 == bd && i2 < bi)) { bd = d2; bi = i2; }
        }
        idx_s[tid] = bi;
        g_idx[v0 + tid] = bi;
    }
    __syncthreads();
    for (int i = tid; i < 8192; i += 256) {
        int d = i >> 6, vl = i & 63;
        zq[(b * DIM + d) * 4096 + s0 + vl] = __ldg(&emb[idx_s[vl] * DIM + d]);
    }
}

// deconv1 gather (unchanged)
__global__ __launch_bounds__(256) void deconv1_gather_kernel() {
    __shared__ int sidx[6][18];
    int n = blockIdx.z, p0 = blockIdx.y * 8, q0 = blockIdx.x * 32;
    int tid = threadIdx.x;
    int rb = p0 / 2 - 1, cb = q0 / 2 - 1;
    for (int i = tid; i < 108; i += 256) {
        int r = i / 18, c = i - r * 18;
        int rr = rb + r, cc = cb + c;
        sidx[r][c] = ((unsigned)rr < H2 && (unsigned)cc < H2)
                     ? g_idx[n * 4096 + rr * 64 + cc] : 512;
    }
    __syncthreads();
    int oc = tid & 127, half = tid >> 7;
    const float* Toc = g_T + oc;
#pragma unroll
    for (int s = 0; s < 4; s++) {
        int pl = half * 4 + s, p = p0 + pl;
        int a4 = (p & 1) * 4;
        int rl = (pl + (p & 1)) >> 1;
        const int* r0 = sidx[rl];
        const int* r1 = sidx[rl + 1];
        float* op = g_g + ((n * DIM + oc) * H1 + p) * H1 + q0;
        for (int jj = 0; jj < 32; jj += 4) {
            int cl = jj >> 1;
            int k00 = r0[cl], k01 = r0[cl + 1], k02 = r0[cl + 2], k03 = r0[cl + 3];
            int k10 = r1[cl], k11 = r1[cl + 1], k12 = r1[cl + 2], k13 = r1[cl + 3];
            float4 v;
            v.x = __ldg(&Toc[(k00 * 16 + a4)     * 128]) + __ldg(&Toc[(k01 * 16 + a4 + 2)  * 128])
                + __ldg(&Toc[(k10 * 16 + a4 + 8) * 128]) + __ldg(&Toc[(k11 * 16 + a4 + 10) * 128]);
            v.y = __ldg(&Toc[(k01 * 16 + a4 + 1) * 128]) + __ldg(&Toc[(k02 * 16 + a4 + 3)  * 128])
                + __ldg(&Toc[(k11 * 16 + a4 + 9) * 128]) + __ldg(&Toc[(k12 * 16 + a4 + 11) * 128]);
            v.z = __ldg(&Toc[(k01 * 16 + a4)     * 128]) + __ldg(&Toc[(k02 * 16 + a4 + 2)  * 128])
                + __ldg(&Toc[(k11 * 16 + a4 + 8) * 128]) + __ldg(&Toc[(k12 * 16 + a4 + 10) * 128]);
            v.w = __ldg(&Toc[(k02 * 16 + a4 + 1) * 128]) + __ldg(&Toc[(k03 * 16 + a4 + 3)  * 128])
                + __ldg(&Toc[(k12 * 16 + a4 + 9) * 128]) + __ldg(&Toc[(k13 * 16 + a4 + 11) * 128]);
            v.x = fmaxf(v.x, 0.f); v.y = fmaxf(v.y, 0.f);
            v.z = fmaxf(v.z, 0.f); v.w = fmaxf(v.w, 0.f);
            *(float4*)(op + jj) = v;
        }
    }
}

// deconv2: R11-passing version (static smem weights, cp.async inputs).
__global__ __launch_bounds__(256) void deconv2_kernel(
    const float* __restrict__ w, float* __restrict__ recon) {
    __shared__ float wsp[CIN * DIM * 16];
    __shared__ float insb[2][1600];
    int n = blockIdx.z;
    int p0 = blockIdx.y * 16, q0 = blockIdx.x * 32;
    int tid = threadIdx.x, pl = tid >> 4, qi = tid & 15;
    int qp = qi & 1, jj = qi >> 1, a = pl & 1;
    int r0l = (pl + a) >> 1, c0l = qp + 2 * jj;
    int rb = p0 / 2 - 1, cb = q0 / 2 - 1;
    for (int i = tid; i < CIN * DIM * 16; i += 256) {
        int oc = i >> 11, rem = i & 2047;
        int ic = rem >> 4, k = rem & 15, kh = k >> 2, kw = k & 3;
        int slot = ic * 16 + ((kh & 1) * 2 + (kw & 1)) * 4 + ((kh >> 1) << 1) + (kw >> 1);
        wsp[oc * 2048 + slot] = w[i];
    }
    for (int i = tid; i < 1440; i += 256) {
        int ic = i / 180, rem = i - ic * 180, r = rem / 18, c = rem - r * 18;
        int rr = rb + r, cc = cb + c;
        bool ok = ((unsigned)rr < H1) && ((unsigned)cc < H1);
        const float* src = ok ? &g_g[((n * DIM + ic) * H1 + rr) * H1 + cc] : g_g;
        cp4z(cvta_s(&insb[0][ic * 200 + r * 20 + c]), src, ok ? 4 : 0);
    }
    CP_COMMIT();

    u64 acc[3] = {0, 0, 0};
    for (int s = 0; s < 16; s++) {
        CP_WAIT0();
        __syncthreads();
        if (s < 15) {
            int ic0 = (s + 1) * 8;
            float* nb = insb[(s + 1) & 1];
            for (int i = tid; i < 1440; i += 256) {
                int ic = i / 180, rem = i - ic * 180, r = rem / 18, c = rem - r * 18;
                int rr = rb + r, cc = cb + c;
                bool ok = ((unsigned)rr < H1) && ((unsigned)cc < H1);
                const float* src = ok ? &g_g[((n * DIM + ic0 + ic) * H1 + rr) * H1 + cc] : g_g;
                cp4z(cvta_s(nb + ic * 200 + r * 20 + c), src, ok ? 4 : 0);
            }
            CP_COMMIT();
        }
        const float* buf = insb[s & 1];
        int ic0 = s * 8;
#pragma unroll
        for (int icl = 0; icl < 8; icl++) {
            const float* rp0 = buf + icl * 200 + r0l * 20;
            float t00 = rp0[c0l], t01 = rp0[c0l + 1], t02 = rp0[c0l + 2];
            float t10 = rp0[20 + c0l], t11 = rp0[20 + c0l + 1], t12 = rp0[20 + c0l + 2];
            u64 i0a = pack2(t00, t01), i0b = pack2(t01, t02);
            u64 i1a = pack2(t10, t11), i1b = pack2(t11, t12);
            int kb = (ic0 + icl) * 16 + (a * 2 + qp) * 4;
#pragma unroll
            for (int o = 0; o < 3; o++) {
                float4 wg = *(const float4*)&wsp[o * 2048 + kb];
                fma2(acc[o], i0a, pack2(wg.x, wg.x)); fma2(acc[o], i0b, pack2(wg.y, wg.y));
                fma2(acc[o], i1a, pack2(wg.z, wg.z)); fma2(acc[o], i1b, pack2(wg.w, wg.w));
            }
        }
    }
    int p = p0 + pl, q = q0 + qp + 4 * jj;
#pragma unroll
    for (int o = 0; o < 3; o++) {
        float2 v = unpack2(acc[o]);
        float* op = recon + ((n * CIN + o) * H0 + p) * H0;
        op[q] = tanhf(v.x);
        op[q + 2] = tanhf(v.y);
    }
}

#define VQ_SMEM ((128 * 68 + 128 * 132) * (int)sizeof(float))

extern "C" void kernel_launch(void* const* d_in, const int* in_sizes, int n_in,
                              void* d_out, int out_size) {
    const float* x    = (const float*)d_in[0];
    const float* w_e1 = (const float*)d_in[1];
    const float* w_e2 = (const float*)d_in[2];
    const float* emb  = (const float*)d_in[3];
    const float* w_d1 = (const float*)d_in[4];
    const float* w_d2 = (const float*)d_in[5];
    float* out = (float*)d_out;
    float* recon = out;
    float* ze = out + OFF_ZE;
    float* zq = out + OFF_ZQ;

    cudaFuncSetAttribute(vq_kernel, cudaFuncAttributeMaxDynamicSharedMemorySize, VQ_SMEM);
    cudaFuncSetAttribute(conv2_kernel, cudaFuncAttributeMaxDynamicSharedMemorySize, C2_SMEM);

    knorm_kernel<<<2, 256>>>(emb);
    tmat_kernel<<<128, 256>>>(emb, w_d1);
    conv1_kernel<<<dim3(H1, B), 256>>>(x, w_e1);
    conv2_kernel<<<dim3(8, 8, B), 256, C2_SMEM>>>(w_e2, ze);
    vq_kernel<<<1024, 256, VQ_SMEM>>>(ze, emb, zq);
    deconv1_gather_kernel<<<dim3(4, 16, B), 256>>>();
    deconv2_kernel<<<dim3(8, 16, B), 256>>>(w_d2, recon);
}

// round 14
// speedup vs baseline: 2.3064x; 1.0071x over previous
#include <cuda_runtime.h>
#include <math.h>

#define B 16
#define CIN 3
#define DIM 128
#define KCODES 512
#define H0 256
#define H1 128
#define H2 64
#define OFF_ZE  (B*CIN*H0*H0)
#define OFF_ZQ  (OFF_ZE + B*DIM*H2*H2)

__device__ float g_h[B*DIM*H1*H1];
__device__ float g_g[B*DIM*H1*H1];
__device__ float g_cnorm[KCODES];
__device__ int   g_idx[B*H2*H2];
__device__ float g_T[513*16*128];

typedef unsigned long long u64;
typedef unsigned int u32;
__device__ __forceinline__ void fma2(u64& d, u64 a, u64 b) {
    asm("fma.rn.f32x2 %0, %1, %2, %0;" : "+l"(d) : "l"(a), "l"(b));
}
__device__ __forceinline__ u64 pack2(float lo, float hi) {
    u64 r; asm("mov.b64 %0, {%1, %2};" : "=l"(r) : "f"(lo), "f"(hi)); return r;
}
__device__ __forceinline__ float2 unpack2(u64 v) {
    float2 r; asm("mov.b64 {%0, %1}, %2;" : "=f"(r.x), "=f"(r.y) : "l"(v)); return r;
}
__device__ __forceinline__ u64 lds2(const float* p) { return *(const u64*)p; }
__device__ __forceinline__ u32 cvta_s(const void* p) {
    u32 a; asm("{.reg .u64 t; cvta.to.shared.u64 t, %1; cvt.u32.u64 %0, t;}" : "=r"(a) : "l"(p));
    return a;
}
__device__ __forceinline__ void cp16(u32 d, const void* s) {
    asm volatile("cp.async.ca.shared.global [%0], [%1], 16;" :: "r"(d), "l"(s));
}
__device__ __forceinline__ void cp4z(u32 d, const void* s, int sz) {
    asm volatile("cp.async.ca.shared.global [%0], [%1], 4, %2;" :: "r"(d), "l"(s), "r"(sz));
}
#define CP_COMMIT() asm volatile("cp.async.commit_group;" ::: "memory")
#define CP_WAIT0()  asm volatile("cp.async.wait_group 0;" ::: "memory")

__global__ void knorm_kernel(const float* __restrict__ emb) {
    int k = blockIdx.x * blockDim.x + threadIdx.x;
    if (k < KCODES) {
        const float* e = emb + k * DIM;
        float s = 0.f;
#pragma unroll 8
        for (int d = 0; d < DIM; d++) s += e[d] * e[d];
        g_cnorm[k] = s;
    }
}

__global__ __launch_bounds__(256) void tmat_kernel(
    const float* __restrict__ emb, const float* __restrict__ wd1) {
    __shared__ float ws[2048];
    int oc = blockIdx.x, tid = threadIdx.x;
    for (int i = tid; i < 2048; i += 256) ws[i] = wd1[oc * 2048 + i];
    __syncthreads();
    for (int k = tid; k < 513; k += 256) {
        float acc[16];
#pragma unroll
        for (int t = 0; t < 16; t++) acc[t] = 0.f;
        if (k < 512) {
            const float* e = emb + k * DIM;
            for (int ic = 0; ic < 128; ic++) {
                float ev = __ldg(e + ic);
                const float* wp = &ws[ic * 16];
#pragma unroll
                for (int t = 0; t < 16; t++) acc[t] += ev * wp[t];
            }
        }
#pragma unroll
        for (int t = 0; t < 16; t++) g_T[(k * 16 + t) * 128 + oc] = acc[t];
    }
}

// conv1: 2 oy rows per block; per-output chains identical to R13.
__global__ __launch_bounds__(256) void conv1_kernel(
    const float* __restrict__ x, const float* __restrict__ w) {
    __shared__ float ws[DIM * 48];
    __shared__ float ins[CIN][6][260];
    int n = blockIdx.y, oy0 = blockIdx.x * 2, tid = threadIdx.x;
    for (int i = tid; i < DIM * 48; i += 256) ws[i] = w[i];
    int iyb = oy0 * 2 - 1;
    for (int i = tid; i < CIN * 6 * 258; i += 256) {
        int ic = i / 1548, rem = i - ic * 1548, r = rem / 258, c = rem - r * 258;
        int iy = iyb + r, ix = c - 1;
        float v = 0.f;
        if ((unsigned)iy < H0 && (unsigned)ix < H0) v = x[((n * CIN + ic) * H0 + iy) * H0 + ix];
        ins[ic][r][c] = v;
    }
    __syncthreads();
    int oc = tid >> 1, half = tid & 1;
    u64 wp[24];
#pragma unroll
    for (int ic = 0; ic < 3; ic++)
#pragma unroll
        for (int kh = 0; kh < 4; kh++) {
            const float* wk = &ws[oc * 48 + ic * 16 + kh * 4];
            wp[(ic * 4 + kh) * 2] = pack2(wk[0], wk[1]);
            wp[(ic * 4 + kh) * 2 + 1] = pack2(wk[2], wk[3]);
        }
#pragma unroll
    for (int ry = 0; ry < 2; ry++) {
        float* outp = g_h + ((n * DIM + oc) * H1 + oy0 + ry) * H1;
        for (int k = 0; k < 64; k += 4) {
            int oxa = half + 2 * k;
            u64 a0 = 0, a1 = 0, a2 = 0, a3 = 0;
#pragma unroll
            for (int ic = 0; ic < 3; ic++)
#pragma unroll
                for (int kh = 0; kh < 4; kh++) {
                    const float* rp = &ins[ic][2 * ry + kh][2 * oxa];
                    u64 w01 = wp[(ic * 4 + kh) * 2], w23 = wp[(ic * 4 + kh) * 2 + 1];
                    fma2(a0, lds2(rp),      w01); fma2(a0, lds2(rp + 2),  w23);
                    fma2(a1, lds2(rp + 4),  w01); fma2(a1, lds2(rp + 6),  w23);
                    fma2(a2, lds2(rp + 8),  w01); fma2(a2, lds2(rp + 10), w23);
                    fma2(a3, lds2(rp + 12), w01); fma2(a3, lds2(rp + 14), w23);
                }
            float2 v0 = unpack2(a0), v1 = unpack2(a1), v2 = unpack2(a2), v3 = unpack2(a3);
            outp[oxa]     = fmaxf(v0.x + v0.y, 0.f);
            outp[oxa + 2] = fmaxf(v1.x + v1.y, 0.f);
            outp[oxa + 4] = fmaxf(v2.x + v2.y, 0.f);
            outp[oxa + 6] = fmaxf(v3.x + v3.y, 0.f);
        }
    }
}

// conv2 (unchanged from R13 — at its FFMA2 floor)
#define C2_TBL_F 3072
#define C2_WS_F  8704
#define C2_BUF_F (C2_WS_F + 1584)
#define C2_SMEM  ((C2_TBL_F + 2 * C2_BUF_F) * 4)

__global__ __launch_bounds__(256, 2) void conv2_kernel(
    const float* __restrict__ w, float* __restrict__ ze) {
    extern __shared__ float s2[];
    uint2* tbl = (uint2*)s2;
    float* bufs = s2 + C2_TBL_F;
    int tid = threadIdx.x;
    int n = blockIdx.z, oy0 = blockIdx.y * 8, ox0 = blockIdx.x * 8;
    int ocg = tid >> 3, oyl = tid & 7;
    int iyb = oy0 * 2 - 1, ixb = ox0 * 2 - 1;
    u32 sbase = cvta_s(bufs);

    uint2* myt = tbl + tid * 6;
#pragma unroll
    for (int j = 0; j < 6; j++) {
        int i = tid + j * 256;
        u32 gof = 0, sof = (u32)((C2_WS_F + 19) * 4);
        if (i < 1296) {
            int ic = i / 324, rem = i - ic * 324, r = rem / 18, c = rem - r * 18;
            int iy = iyb + r, ix = ixb + c;
            bool ok = ((unsigned)iy < H1) && ((unsigned)ix < H1);
            sof = (u32)((C2_WS_F + ic * 396 + r * 22 + c) * 4) | (ok ? 1u : 0u);
            if (ok) gof = (u32)(((n * DIM + ic) * H1 + iy) * H1 + ix);
        }
        myt[j] = make_uint2(gof, sof);
    }
    int woc0 = tid >> 4;
    u32 wdofs = (u32)(woc0 * 68 * 4 + (tid & 15) * 16);
    const float* wsrc = w + woc0 * 2048 + (tid & 15) * 4;

    u64 acc[4][8];
#pragma unroll
    for (int o = 0; o < 4; o++)
#pragma unroll
        for (int j = 0; j < 8; j++) acc[o][j] = 0;

    {
        u32 bb = sbase;
#pragma unroll
        for (int jj = 0; jj < 8; jj++)
            cp16(bb + wdofs + jj * (16 * 68 * 4), wsrc + jj * (16 * 2048));
#pragma unroll
        for (int jj = 0; jj < 5; jj++) {
            uint2 e = myt[jj];
            cp4z(bb + (e.y & ~1u), g_h + e.x, (e.y & 1) * 4);
        }
        if (tid < 16) {
            uint2 e = myt[5];
            cp4z(bb + (e.y & ~1u), g_h + e.x, (e.y & 1) * 4);
        }
    }
    CP_COMMIT();

    for (int st = 0; st < 32; st++) {
        CP_WAIT0();
        __syncthreads();
        if (st < 31) {
            u32 bb = sbase + ((st + 1) & 1) * (C2_BUF_F * 4);
            const float* wsp = wsrc + (st + 1) * 64;
            const float* gbase = g_h + (st + 1) * 65536;
#pragma unroll
            for (int jj = 0; jj < 8; jj++)
                cp16(bb + wdofs + jj * (16 * 68 * 4), wsp + jj * (16 * 2048));
#pragma unroll
            for (int jj = 0; jj < 5; jj++) {
                uint2 e = myt[jj];
                cp4z(bb + (e.y & ~1u), gbase + e.x, (e.y & 1) * 4);
            }
            if (tid < 16) {
                uint2 e = myt[5];
                cp4z(bb + (e.y & ~1u), gbase + e.x, (e.y & 1) * 4);
            }
            CP_COMMIT();
        }
        float* wsb = bufs + (st & 1) * C2_BUF_F;
        float* insb = wsb + C2_WS_F;
#pragma unroll
        for (int icl = 0; icl < 4; icl++) {
#pragma unroll
            for (int kh = 0; kh < 4; kh++) {
                const float* rp = insb + icl * 396 + (oyl * 2 + kh) * 22;
                u64 ivp[9];
#pragma unroll
                for (int m = 0; m < 9; m++) ivp[m] = lds2(rp + 2 * m);
#pragma unroll
                for (int o = 0; o < 4; o++) {
                    const ulonglong2* wpt = (const ulonglong2*)
                        (wsb + (ocg * 4 + o) * 68 + icl * 16 + kh * 4);
                    ulonglong2 wv = *wpt;
#pragma unroll
                    for (int j = 0; j < 8; j++) {
                        fma2(acc[o][j], ivp[j], wv.x);
                        fma2(acc[o][j], ivp[j + 1], wv.y);
                    }
                }
            }
        }
    }
    int oy = oy0 + oyl;
#pragma unroll
    for (int o = 0; o < 4; o++) {
        float* op = ze + ((n * DIM + ocg * 4 + o) * H2 + oy) * H2 + ox0;
#pragma unroll
        for (int j = 0; j < 8; j++) {
            float2 v = unpack2(acc[o][j]);
            op[j] = v.x + v.y;
        }
    }
}

// VQ (unchanged)
__global__ __launch_bounds__(256) void vq_kernel(
    const float* __restrict__ ze, const float* __restrict__ emb, float* __restrict__ zq) {
    extern __shared__ float sm[];
    float* z_s = sm;
    float* c_s = sm + 128 * 68;
    __shared__ int idx_s[64];
    int tid = threadIdx.x;
    int v0 = blockIdx.x * 64, b = v0 >> 12, s0 = v0 & 4095;
    for (int i = tid; i < 2048; i += 256) {
        int d = i >> 4, vl4 = (i & 15) * 4;
        *(float4*)&z_s[d * 68 + vl4] = *(const float4*)&ze[(b * DIM + d) * 4096 + s0 + vl4];
    }
    int vg = tid >> 4, cg = tid & 15;
    float minv[4]; int mini[4];
#pragma unroll
    for (int v = 0; v < 4; v++) { minv[v] = 3.0e38f; mini[v] = 0; }
    u64 dot[2][8];
#pragma unroll
    for (int vp = 0; vp < 2; vp++)
#pragma unroll
        for (int c = 0; c < 8; c++) dot[vp][c] = 0;
    for (int ch = 0; ch < 4; ch++) {
        __syncthreads();
        int cbase = ch * 128;
        for (int i = tid; i < 4096; i += 256) {
            int cl = i & 127, dq = (i >> 7) * 4;
            float4 t = *(const float4*)&emb[(cbase + cl) * DIM + dq];
            c_s[dq * 132 + cl] = t.x; c_s[(dq + 1) * 132 + cl] = t.y;
            c_s[(dq + 2) * 132 + cl] = t.z; c_s[(dq + 3) * 132 + cl] = t.w;
        }
        __syncthreads();
#pragma unroll 2
        for (int d = 0; d < 128; d++) {
            const float* zp = &z_s[d * 68 + vg * 4];
            float4 z0 = *(const float4*)zp;
            u64 zpk[2] = {pack2(z0.x, z0.y), pack2(z0.z, z0.w)};
            const float* cp = &c_s[d * 132];
            float4 c0 = *(const float4*)(cp + cg * 4), c1 = *(const float4*)(cp + 64 + cg * 4);
            u64 cb[8] = {pack2(c0.x, c0.x), pack2(c0.y, c0.y), pack2(c0.z, c0.z), pack2(c0.w, c0.w),
                         pack2(c1.x, c1.x), pack2(c1.y, c1.y), pack2(c1.z, c1.z), pack2(c1.w, c1.w)};
#pragma unroll
            for (int vp = 0; vp < 2; vp++)
#pragma unroll
                for (int c = 0; c < 8; c++) fma2(dot[vp][c], zpk[vp], cb[c]);
        }
#pragma unroll
        for (int c = 0; c < 8; c++) {
            int code = cbase + (c < 4 ? cg * 4 + c : 64 + cg * 4 + (c - 4));
            float cn = g_cnorm[code];
#pragma unroll
            for (int vp = 0; vp < 2; vp++) {
                float2 dv = unpack2(dot[vp][c]);
                float d0 = fmaf(-2.f, dv.x, cn), d1 = fmaf(-2.f, dv.y, cn);
                if (d0 < minv[2 * vp]) { minv[2 * vp] = d0; mini[2 * vp] = code; }
                if (d1 < minv[2 * vp + 1]) { minv[2 * vp + 1] = d1; mini[2 * vp + 1] = code; }
                dot[vp][c] = 0;
            }
        }
    }
    __syncthreads();
    float* rd = c_s; int* ri = (int*)(c_s + 1024);
#pragma unroll
    for (int v = 0; v < 4; v++) {
        int vl = vg * 4 + v;
        rd[vl * 16 + cg] = minv[v]; ri[vl * 16 + cg] = mini[v];
    }
    __syncthreads();
    if (tid < 64) {
        float bd = rd[tid * 16]; int bi = ri[tid * 16];
        for (int g = 1; g < 16; g++) {
            float d2 = rd[tid * 16 + g]; int i2 = ri[tid * 16 + g];
            if (d2 < bd || (d2 == bd && i2 < bi)) { bd = d2; bi = i2; }
        }
        idx_s[tid] = bi;
        g_idx[v0 + tid] = bi;
    }
    __syncthreads();
    for (int i = tid; i < 8192; i += 256) {
        int d = i >> 6, vl = i & 63;
        zq[(b * DIM + d) * 4096 + s0 + vl] = __ldg(&emb[idx_s[vl] * DIM + d]);
    }
}

// deconv1 gather (unchanged)
__global__ __launch_bounds__(256) void deconv1_gather_kernel() {
    __shared__ int sidx[6][18];
    int n = blockIdx.z, p0 = blockIdx.y * 8, q0 = blockIdx.x * 32;
    int tid = threadIdx.x;
    int rb = p0 / 2 - 1, cb = q0 / 2 - 1;
    for (int i = tid; i < 108; i += 256) {
        int r = i / 18, c = i - r * 18;
        int rr = rb + r, cc = cb + c;
        sidx[r][c] = ((unsigned)rr < H2 && (unsigned)cc < H2)
                     ? g_idx[n * 4096 + rr * 64 + cc] : 512;
    }
    __syncthreads();
    int oc = tid & 127, half = tid >> 7;
    const float* Toc = g_T + oc;
#pragma unroll
    for (int s = 0; s < 4; s++) {
        int pl = half * 4 + s, p = p0 + pl;
        int a4 = (p & 1) * 4;
        int rl = (pl + (p & 1)) >> 1;
        const int* r0 = sidx[rl];
        const int* r1 = sidx[rl + 1];
        float* op = g_g + ((n * DIM + oc) * H1 + p) * H1 + q0;
        for (int jj = 0; jj < 32; jj += 4) {
            int cl = jj >> 1;
            int k00 = r0[cl], k01 = r0[cl + 1], k02 = r0[cl + 2], k03 = r0[cl + 3];
            int k10 = r1[cl], k11 = r1[cl + 1], k12 = r1[cl + 2], k13 = r1[cl + 3];
            float4 v;
            v.x = __ldg(&Toc[(k00 * 16 + a4)     * 128]) + __ldg(&Toc[(k01 * 16 + a4 + 2)  * 128])
                + __ldg(&Toc[(k10 * 16 + a4 + 8) * 128]) + __ldg(&Toc[(k11 * 16 + a4 + 10) * 128]);
            v.y = __ldg(&Toc[(k01 * 16 + a4 + 1) * 128]) + __ldg(&Toc[(k02 * 16 + a4 + 3)  * 128])
                + __ldg(&Toc[(k11 * 16 + a4 + 9) * 128]) + __ldg(&Toc[(k12 * 16 + a4 + 11) * 128]);
            v.z = __ldg(&Toc[(k01 * 16 + a4)     * 128]) + __ldg(&Toc[(k02 * 16 + a4 + 2)  * 128])
                + __ldg(&Toc[(k11 * 16 + a4 + 8) * 128]) + __ldg(&Toc[(k12 * 16 + a4 + 10) * 128]);
            v.w = __ldg(&Toc[(k02 * 16 + a4 + 1) * 128]) + __ldg(&Toc[(k03 * 16 + a4 + 3)  * 128])
                + __ldg(&Toc[(k12 * 16 + a4 + 9) * 128]) + __ldg(&Toc[(k13 * 16 + a4 + 11) * 128]);
            v.x = fmaxf(v.x, 0.f); v.y = fmaxf(v.y, 0.f);
            v.z = fmaxf(v.z, 0.f); v.w = fmaxf(v.w, 0.f);
            *(float4*)(op + jj) = v;
        }
    }
}

// deconv2: 32p x 32q tile; thread computes p and p+16 (same parity a, same kb).
__global__ __launch_bounds__(256) void deconv2_kernel(
    const float* __restrict__ w, float* __restrict__ recon) {
    __shared__ float wsp[CIN * DIM * 16];
    __shared__ float insb[2][2880];   // 8 ic x 18 rows x 20 pitch
    int n = blockIdx.z;
    int p0 = blockIdx.y * 32, q0 = blockIdx.x * 32;
    int tid = threadIdx.x, pl = tid >> 4, qi = tid & 15;
    int qp = qi & 1, jj = qi >> 1, a = pl & 1;
    int r0l = (pl + a) >> 1, c0l = qp + 2 * jj;
    int rb = p0 / 2 - 1, cb = q0 / 2 - 1;
    for (int i = tid; i < CIN * DIM * 16; i += 256) {
        int oc = i >> 11, rem = i & 2047;
        int ic = rem >> 4, k = rem & 15, kh = k >> 2, kw = k & 3;
        int slot = ic * 16 + ((kh & 1) * 2 + (kw & 1)) * 4 + ((kh >> 1) << 1) + (kw >> 1);
        wsp[oc * 2048 + slot] = w[i];
    }
    for (int i = tid; i < 2592; i += 256) {
        int ic = i / 324, rem = i - ic * 324, r = rem / 18, c = rem - r * 18;
        int rr = rb + r, cc = cb + c;
        bool ok = ((unsigned)rr < H1) && ((unsigned)cc < H1);
        const float* src = ok ? &g_g[((n * DIM + ic) * H1 + rr) * H1 + cc] : g_g;
        cp4z(cvta_s(&insb[0][ic * 360 + r * 20 + c]), src, ok ? 4 : 0);
    }
    CP_COMMIT();

    u64 acc[2][3] = {{0, 0, 0}, {0, 0, 0}};
    for (int s = 0; s < 16; s++) {
        CP_WAIT0();
        __syncthreads();
        if (s < 15) {
            int ic0 = (s + 1) * 8;
            float* nb = insb[(s + 1) & 1];
            for (int i = tid; i < 2592; i += 256) {
                int ic = i / 324, rem = i - ic * 324, r = rem / 18, c = rem - r * 18;
                int rr = rb + r, cc = cb + c;
                bool ok = ((unsigned)rr < H1) && ((unsigned)cc < H1);
                const float* src = ok ? &g_g[((n * DIM + ic0 + ic) * H1 + rr) * H1 + cc] : g_g;
                cp4z(cvta_s(nb + ic * 360 + r * 20 + c), src, ok ? 4 : 0);
            }
            CP_COMMIT();
        }
        const float* buf = insb[s & 1];
        int ic0 = s * 8;
#pragma unroll
        for (int icl = 0; icl < 8; icl++) {
            const float* rpa = buf + icl * 360 + r0l * 20;
            const float* rpb = rpa + 160;   // rows r0l+8, r0l+9
            float t00 = rpa[c0l], t01 = rpa[c0l + 1], t02 = rpa[c0l + 2];
            float t10 = rpa[20 + c0l], t11 = rpa[20 + c0l + 1], t12 = rpa[20 + c0l + 2];
            float u00 = rpb[c0l], u01 = rpb[c0l + 1], u02 = rpb[c0l + 2];
            float u10 = rpb[20 + c0l], u11 = rpb[20 + c0l + 1], u12 = rpb[20 + c0l + 2];
            u64 i0a = pack2(t00, t01), i0b = pack2(t01, t02);
            u64 i1a = pack2(t10, t11), i1b = pack2(t11, t12);
            u64 j0a = pack2(u00, u01), j0b = pack2(u01, u02);
            u64 j1a = pack2(u10, u11), j1b = pack2(u11, u12);
            int kb = (ic0 + icl) * 16 + (a * 2 + qp) * 4;
#pragma unroll
            for (int o = 0; o < 3; o++) {
                float4 wg = *(const float4*)&wsp[o * 2048 + kb];
                u64 wx = pack2(wg.x, wg.x), wy = pack2(wg.y, wg.y);
                u64 wz = pack2(wg.z, wg.z), ww = pack2(wg.w, wg.w);
                fma2(acc[0][o], i0a, wx); fma2(acc[0][o], i0b, wy);
                fma2(acc[0][o], i1a, wz); fma2(acc[0][o], i1b, ww);
                fma2(acc[1][o], j0a, wx); fma2(acc[1][o], j0b, wy);
                fma2(acc[1][o], j1a, wz); fma2(acc[1][o], j1b, ww);
            }
        }
    }
    int q = q0 + qp + 4 * jj;
#pragma unroll
    for (int h = 0; h < 2; h++) {
        int p = p0 + pl + h * 16;
#pragma unroll
        for (int o = 0; o < 3; o++) {
            float2 v = unpack2(acc[h][o]);
            float* op = recon + ((n * CIN + o) * H0 + p) * H0;
            op[q] = tanhf(v.x);
            op[q + 2] = tanhf(v.y);
        }
    }
}

#define VQ_SMEM ((128 * 68 + 128 * 132) * (int)sizeof(float))

extern "C" void kernel_launch(void* const* d_in, const int* in_sizes, int n_in,
                              void* d_out, int out_size) {
    const float* x    = (const float*)d_in[0];
    const float* w_e1 = (const float*)d_in[1];
    const float* w_e2 = (const float*)d_in[2];
    const float* emb  = (const float*)d_in[3];
    const float* w_d1 = (const float*)d_in[4];
    const float* w_d2 = (const float*)d_in[5];
    float* out = (float*)d_out;
    float* recon = out;
    float* ze = out + OFF_ZE;
    float* zq = out + OFF_ZQ;

    cudaFuncSetAttribute(vq_kernel, cudaFuncAttributeMaxDynamicSharedMemorySize, VQ_SMEM);
    cudaFuncSetAttribute(conv2_kernel, cudaFuncAttributeMaxDynamicSharedMemorySize, C2_SMEM);

    knorm_kernel<<<2, 256>>>(emb);
    tmat_kernel<<<128, 256>>>(emb, w_d1);
    conv1_kernel<<<dim3(64, B), 256>>>(x, w_e1);
    conv2_kernel<<<dim3(8, 8, B), 256, C2_SMEM>>>(w_e2, ze);
    vq_kernel<<<1024, 256, VQ_SMEM>>>(ze, emb, zq);
    deconv1_gather_kernel<<<dim3(4, 16, B), 256>>>();
    deconv2_kernel<<<dim3(8, 8, B), 256>>>(w_d2, recon);
}